// round 11
// baseline (speedup 1.0000x reference)
#include <cuda_runtime.h>
#include <cuda_bf16.h>
#include <stdint.h>

#define Bn 2
#define Nn 2048
#define Kn 48
#define Cn 128
#define TILES (Bn * Nn / 2)

// ---------------- device scratch ----------------
__device__ __nv_bfloat16 g_W1c[128 * 128];   // [n][k] = W1[256+k][n]
__device__ __nv_bfloat16 g_W2t[128 * 128];   // [n][k]
__device__ __nv_bfloat16 g_edge_bf[(size_t)Bn * Nn * Kn * Cn];  // 50 MB bf16 edges
__device__ float g_Pi[Bn * Nn * Cn];         // node_h @ W1[0:128] + b1
__device__ float g_Pj[Bn * Nn * Cn];         // node_h @ W1[128:256]
__device__ float g_sumh2[Bn * Nn * Cn];      // per-node sum of gelu(h2) over K edges
__device__ int   g_joff[Bn * Nn * Kn];       // precomputed gather row: b*Nn + j

// ---------------- helpers ----------------
__device__ __forceinline__ uint32_t smem_u32(const void* p) {
    uint32_t a;
    asm("{ .reg .u64 t; cvta.to.shared.u64 t, %1; cvt.u32.u64 %0, t; }" : "=r"(a) : "l"(p));
    return a;
}
__device__ __forceinline__ unsigned pk2(float a, float b) {
    __nv_bfloat162 t = __floats2bfloat162_rn(a, b);
    return *reinterpret_cast<unsigned*>(&t);
}
// tanh-GELU via Eigen/XLA rational tanh: FFMA-dominated, exactly 1 MUFU (rcp)
__device__ __forceinline__ float gelu_fast(float x) {
    float y = x * (0.79788456f + 0.03567741f * x * x);
    y = fminf(fmaxf(y, -7.90531110f), 7.90531110f);
    float y2 = y * y;
    float num = y * (4.89352456e-03f + y2 * (6.37261929e-04f + y2 * (1.48572235e-05f +
                y2 * (5.12229709e-08f + y2 * (-8.60467152e-11f + y2 * (2.00018790e-13f +
                y2 * (-2.76076847e-16f)))))));
    float den = 4.89352519e-03f + y2 * (2.26843464e-03f + y2 * (1.18534706e-04f +
                y2 * 1.19825839e-06f));
    float r;
    asm("rcp.approx.ftz.f32 %0, %1;" : "=f"(r) : "f"(den));
    float hx = 0.5f * x;
    return hx + hx * (num * r);
}
__device__ __forceinline__ void mma16816(float c[4], const uint32_t a[4], const uint32_t b[2]) {
    asm volatile(
        "mma.sync.aligned.m16n8k16.row.col.f32.bf16.bf16.f32 "
        "{%0,%1,%2,%3},{%4,%5,%6,%7},{%8,%9},{%0,%1,%2,%3};"
        : "+f"(c[0]), "+f"(c[1]), "+f"(c[2]), "+f"(c[3])
        : "r"(a[0]), "r"(a[1]), "r"(a[2]), "r"(a[3]), "r"(b[0]), "r"(b[1]));
}
__device__ __forceinline__ void ldsm4(uint32_t r[4], uint32_t addr) {
    asm volatile("ldmatrix.sync.aligned.m8n8.x4.shared.b16 {%0,%1,%2,%3}, [%4];"
                 : "=r"(r[0]), "=r"(r[1]), "=r"(r[2]), "=r"(r[3]) : "r"(addr));
}
__device__ __forceinline__ void cp16(uint32_t dst, const void* src) {
    asm volatile("cp.async.cg.shared.global [%0], [%1], 16;" :: "r"(dst), "l"(src) : "memory");
}
#define CP_COMMIT() asm volatile("cp.async.commit_group;" ::: "memory")
#define CP_WAIT(N)  asm volatile("cp.async.wait_group %0;" :: "n"(N) : "memory")
// named barrier: 256 threads of one wm-group
#define BAR_GRP(id) asm volatile("bar.sync %0, 256;" :: "r"(id) : "memory")

// XOR-swizzled bf16 tile: 256B rows, 16B chunks; conflict-free ldmatrix, no padding
__device__ __forceinline__ uint32_t phys(int row, int chunk) {
    return (uint32_t)(row * 256 + ((chunk ^ (row & 7)) << 4));
}

// ---------------- pre: conv (edge fp32->bf16) + joff + weight transposes ----------------
__global__ void __launch_bounds__(256)
pre_kernel(const float4* __restrict__ src, const void* __restrict__ edge_index,
           const float* __restrict__ W1, const float* __restrict__ W2) {
    const int bx = blockIdx.x;
    if (bx < 2048) {
        const size_t total = (size_t)Bn * Nn * Kn * 32;   // float4 count
        const size_t step = (size_t)2048 * 256;
        for (size_t i = (size_t)bx * 256 + threadIdx.x; i < total; i += step) {
            float4 v = src[i];
            uint2 p;
            p.x = pk2(v.x, v.y);
            p.y = pk2(v.z, v.w);
            *(uint2*)(g_edge_bf + i * 4) = p;
        }
    } else if (bx < 2144) {
        const unsigned* w = (const unsigned*)edge_index;
        int is64 = 1;
#pragma unroll 1
        for (int t = 1; t < 128; t += 2)
            if (w[t] != 0u) { is64 = 0; break; }
        const long long* idx64 = (const long long*)edge_index;
        const int* idx32 = (const int*)edge_index;
        int base = (bx - 2048) * 2048 + threadIdx.x;
#pragma unroll
        for (int q = 0; q < 8; q++) {
            int e = base + q * 256;
            int j = is64 ? (int)idx64[e] : idx32[e];
            int b = e / (Nn * Kn);
            g_joff[e] = b * Nn + j;
        }
    } else {
        int i = (bx - 2144) * 256 + threadIdx.x;   // 0..32767
        if (i < 16384) {
            int n = i >> 7, k = i & 127;
            g_W1c[i] = __float2bfloat16_rn(W1[(256 + k) * 128 + n]);
        } else {
            int j = i - 16384, n = j >> 7, k = j & 127;
            g_W2t[j] = __float2bfloat16_rn(W2[k * 128 + n]);
        }
    }
}

// ---------------- Pi/Pj precompute (fp32, register-blocked) ----------------
__global__ void __launch_bounds__(256)
pij_kernel(const float* __restrict__ node_h, const float* __restrict__ W1,
           const float* __restrict__ b1) {
    extern __shared__ float sw[];           // Wa 16384 | Wb 16384 | X 4096
    float* sWa = sw;
    float* sWb = sw + 16384;
    float* sX  = sw + 32768;
    int tid = threadIdx.x, lane = tid & 31, warp = tid >> 5;
    for (int i = tid; i < 16384; i += 256) {
        sWa[i] = W1[i];
        sWb[i] = W1[16384 + i];
    }
    int rbase = blockIdx.x * 32;
    for (int i = tid; i < 4096; i += 256)
        sX[i] = node_h[(size_t)rbase * 128 + i];
    __syncthreads();

    int c0 = lane * 4;
    float yi[4][4], yj[4][4];
#pragma unroll
    for (int r = 0; r < 4; r++)
#pragma unroll
        for (int j = 0; j < 4; j++) { yi[r][j] = 0.f; yj[r][j] = 0.f; }

#pragma unroll 4
    for (int k = 0; k < 128; k++) {
        float4 wa = *(const float4*)(sWa + k * 128 + c0);
        float4 wb = *(const float4*)(sWb + k * 128 + c0);
#pragma unroll
        for (int r = 0; r < 4; r++) {
            float x = sX[(warp * 4 + r) * 128 + k];
            yi[r][0] += x * wa.x; yi[r][1] += x * wa.y;
            yi[r][2] += x * wa.z; yi[r][3] += x * wa.w;
            yj[r][0] += x * wb.x; yj[r][1] += x * wb.y;
            yj[r][2] += x * wb.z; yj[r][3] += x * wb.w;
        }
    }
    float4 bv = *(const float4*)(b1 + c0);
#pragma unroll
    for (int r = 0; r < 4; r++) {
        size_t row = (size_t)rbase + warp * 4 + r;
        float4 oi;
        oi.x = yi[r][0] + bv.x; oi.y = yi[r][1] + bv.y;
        oi.z = yi[r][2] + bv.z; oi.w = yi[r][3] + bv.w;
        *(float4*)(g_Pi + row * 128 + c0) = oi;
        float4 oj; oj.x = yj[r][0]; oj.y = yj[r][1]; oj.z = yj[r][2]; oj.w = yj[r][3];
        *(float4*)(g_Pj + row * 128 + c0) = oj;
    }
}

// ---------------- persistent edge-MLP: L1+L2, split into two independent 256-thread groups ----
#define OFF_E0  0
#define OFF_E1  24576
#define OFF_H   49152
#define OFF_PJ  73728          // 96 rows x 132 floats (528B rows) -> 50688
#define OFF_W1  124416
#define OFF_W2  157184
#define OFF_B2  189952
#define OFF_PI  190464         // 2 x 128 floats
#define SMEM_MLP 191488
#define NTHR 512

__global__ void __launch_bounds__(NTHR, 1)
mlp_kernel(const float* __restrict__ b2) {
    extern __shared__ char smem[];
    const uint32_t sb = smem_u32(smem);
    float* sPJ = (float*)(smem + OFF_PJ);
    float* sB2 = (float*)(smem + OFF_B2);
    float* sPi = (float*)(smem + OFF_PI);

    const int tid = threadIdx.x, lane = tid & 31, warp = tid >> 5;
    const int wm = warp >> 3;                 // 0/1 : node within tile = barrier group
    const int wn = warp & 7;                  // 0..7 : 16-col group
    const int r0 = wm * 48;
    const int cq = (lane & 3) * 2;
    const int gtid = tid & 255;               // id within group
    const int barid = 1 + wm;

    // stage weights (swizzled) + b2 (cooperative, full CTA, once)
    for (int i = tid; i < 128 * 16; i += NTHR) {
        int n = i >> 4, ch = (i & 15);
        uint32_t d = phys(n, ch);
        *(uint4*)(smem + OFF_W1 + d) = *(const uint4*)(g_W1c + n * 128 + ch * 8);
        *(uint4*)(smem + OFF_W2 + d) = *(const uint4*)(g_W2t + n * 128 + ch * 8);
    }
    if (tid < 128) sB2[tid] = b2[tid];

    // group-local prefetch: each group copies ONLY its own 48 rows
    auto issue_edges = [&](uint32_t ebuf, int tile) {
        size_t rbase = (size_t)tile * 96 + r0;
#pragma unroll 1
        for (int i = gtid; i < 768; i += 256) {
            int row = i >> 4, ch = i & 15;
            cp16(sb + ebuf + phys(r0 + row, ch), g_edge_bf + (rbase + row) * 128 + ch * 8);
        }
    };
    auto issue_pj = [&](int tile) {
        size_t ibase = (size_t)tile * 96 + r0;
#pragma unroll 1
        for (int i = gtid; i < 1536; i += 256) {
            int row = i >> 5, ch = i & 31;
            int jr = g_joff[ibase + row];
            cp16(sb + OFF_PJ + (r0 + row) * 528 + ch * 16,
                 (const char*)g_Pj + ((size_t)jr << 9) + ch * 16);
        }
    };

    float acc[3][2][4];
    auto run_mma = [&](uint32_t aOff, uint32_t wOff) {
#pragma unroll
        for (int mt = 0; mt < 3; mt++)
#pragma unroll
            for (int nt = 0; nt < 2; nt++)
#pragma unroll
                for (int q = 0; q < 4; q++) acc[mt][nt][q] = 0.f;
#pragma unroll
        for (int kt = 0; kt < 8; kt++) {
            int ch = kt * 2 + (lane >> 4);
            uint32_t rb[4];
            ldsm4(rb, sb + wOff + phys(wn * 16 + (lane & 15), ch));
#pragma unroll
            for (int mt = 0; mt < 3; mt++) {
                uint32_t ra[4];
                ldsm4(ra, sb + aOff + phys(r0 + mt * 16 + (lane & 15), ch));
#pragma unroll
                for (int h = 0; h < 2; h++) {
                    uint32_t bbf[2] = { rb[h], rb[2 + h] };
                    mma16816(acc[mt][h], ra, bbf);
                }
            }
        }
    };

    // ---- initial prefetch: tile t0 (group-local) ----
    int t = blockIdx.x;
    issue_edges(OFF_E0, t); CP_COMMIT();       // A(t0)
    issue_pj(t);            CP_COMMIT();       // B(t0)
    __syncthreads();                           // weights visible to all

    int it = 0;
#pragma unroll 1
    for (; t < TILES; t += gridDim.x, it++) {
        const uint32_t eCur = (it & 1) ? OFF_E1 : OFF_E0;
        const uint32_t eNxt = (it & 1) ? OFF_E0 : OFF_E1;
        const int g0 = t * 2;
        const int tn = t + gridDim.x;
        const bool hn = tn < TILES;

        // a: prefetch next edges (own rows); stage this tile's Pi (own node)
        if (hn) issue_edges(eNxt, tn);
        CP_COMMIT();                            // A(next)
        if (gtid < 128) sPi[wm * 128 + gtid] = g_Pi[(size_t)(g0 + wm) * 128 + gtid];
        CP_WAIT(2);                             // own edges(cur) ready
        BAR_GRP(barid);

        // b: layer 1 MMA (edge part)
        run_mma(eCur, OFF_W1);

        // c: own PJ(cur) ready
        CP_WAIT(1);
        BAR_GRP(barid);

        // d: epi1 = gelu(acc + Pi + Pj) -> H (own rows)
#pragma unroll
        for (int mt = 0; mt < 3; mt++) {
            int r = r0 + mt * 16 + (lane >> 2);
#pragma unroll
            for (int nt = 0; nt < 2; nt++) {
                int c = wn * 16 + nt * 8 + cq;
                float pix = sPi[wm * 128 + c], piy = sPi[wm * 128 + c + 1];
                float h00 = acc[mt][nt][0] + pix + sPJ[r * 132 + c];
                float h01 = acc[mt][nt][1] + piy + sPJ[r * 132 + c + 1];
                float h10 = acc[mt][nt][2] + pix + sPJ[(r + 8) * 132 + c];
                float h11 = acc[mt][nt][3] + piy + sPJ[(r + 8) * 132 + c + 1];
                uint32_t base = phys(r, c >> 3) + (c & 7) * 2;
                uint32_t base8 = phys(r + 8, c >> 3) + (c & 7) * 2;
                *(unsigned*)(smem + OFF_H + base)  = pk2(gelu_fast(h00), gelu_fast(h01));
                *(unsigned*)(smem + OFF_H + base8) = pk2(gelu_fast(h10), gelu_fast(h11));
            }
        }
        BAR_GRP(barid);

        // e: prefetch next PJ (own rows)
        if (hn) issue_pj(tn);
        CP_COMMIT();                            // B(next)

        // f: layer 2 MMA + gelu + row-sum over 48 edges (own node)
        run_mma(OFF_H, OFF_W2);
        float s0[2] = {0.f, 0.f}, s1[2] = {0.f, 0.f};
#pragma unroll
        for (int mt = 0; mt < 3; mt++) {
#pragma unroll
            for (int nt = 0; nt < 2; nt++) {
                int c = wn * 16 + nt * 8 + cq;
                float bb0 = sB2[c], bb1 = sB2[c + 1];
                s0[nt] += gelu_fast(acc[mt][nt][0] + bb0) + gelu_fast(acc[mt][nt][2] + bb0);
                s1[nt] += gelu_fast(acc[mt][nt][1] + bb1) + gelu_fast(acc[mt][nt][3] + bb1);
            }
        }
#pragma unroll
        for (int off = 4; off < 32; off <<= 1)
#pragma unroll
            for (int nt = 0; nt < 2; nt++) {
                s0[nt] += __shfl_xor_sync(0xffffffffu, s0[nt], off);
                s1[nt] += __shfl_xor_sync(0xffffffffu, s1[nt], off);
            }
        if (lane < 4) {
#pragma unroll
            for (int nt = 0; nt < 2; nt++) {
                int c = wn * 16 + nt * 8 + lane * 2;
                float2 v; v.x = s0[nt]; v.y = s1[nt];
                *(float2*)(g_sumh2 + (size_t)(g0 + wm) * 128 + c) = v;
            }
        }
        // loop-top group barrier (phase a) separates f's H reads from next epi1's H writes
    }
}

// ---------------- final: m = sumh2@W3; u = LN(nh + (m+48b3)/30); out = LN(nh + u@Wu + bu)
#define FIN_W3 0
#define FIN_WU 16384
#define FIN_S  32768
#define FIN_U  36864
#define FIN_NH 40960
__global__ void __launch_bounds__(512)
final_kernel(const float* __restrict__ node_h, const float* __restrict__ W3,
             const float* __restrict__ b3, const float* __restrict__ Wu,
             const float* __restrict__ bu, const float* __restrict__ ln_g,
             const float* __restrict__ ln_b, float* __restrict__ out) {
    extern __shared__ float sh[];
    const uint32_t sb = smem_u32(sh);
    float* sW3 = sh + FIN_W3;
    float* sWu = sh + FIN_WU;
    float* sS  = sh + FIN_S;
    float* sU  = sh + FIN_U;
    float* sNH = sh + FIN_NH;
    int tid = threadIdx.x, lane = tid & 31, warp = tid >> 5;
    int rbase = blockIdx.x * 32;

    // group A: W3 + S + NH (phase-1 inputs)
    for (int i = tid; i < 4096; i += 512)
        cp16(sb + (FIN_W3 + i * 4) * 4, W3 + i * 4);
    for (int i = tid; i < 1024; i += 512) {
        cp16(sb + (FIN_S + i * 4) * 4, g_sumh2 + (size_t)rbase * 128 + i * 4);
        cp16(sb + (FIN_NH + i * 4) * 4, node_h + (size_t)rbase * 128 + i * 4);
    }
    CP_COMMIT();
    // group B: Wu (phase-2 input, arrives under phase-1 compute)
    for (int i = tid; i < 4096; i += 512)
        cp16(sb + (FIN_WU + i * 4) * 4, Wu + i * 4);
    CP_COMMIT();

    int c0 = lane * 4;
    float4 gv = *(const float4*)(ln_g + c0);
    float4 lv = *(const float4*)(ln_b + c0);
    float4 b3v = *(const float4*)(b3 + c0);
    float4 bv  = *(const float4*)(bu + c0);

    CP_WAIT(1);
    __syncthreads();

    // phase 1: m = S @ W3 ; u = LN(nh + (m + 48 b3)/30) -> sU   (2 rows/warp)
    float m[2][4];
#pragma unroll
    for (int r = 0; r < 2; r++)
#pragma unroll
        for (int j = 0; j < 4; j++) m[r][j] = 0.f;
#pragma unroll 4
    for (int k = 0; k < 128; k++) {
        float4 w = *(const float4*)(sW3 + k * 128 + c0);
#pragma unroll
        for (int r = 0; r < 2; r++) {
            float s = sS[(warp * 2 + r) * 128 + k];
            m[r][0] += s * w.x; m[r][1] += s * w.y;
            m[r][2] += s * w.z; m[r][3] += s * w.w;
        }
    }
#pragma unroll
    for (int r = 0; r < 2; r++) {
        int rr = warp * 2 + r;
        float4 nh = *(const float4*)(sNH + rr * 128 + c0);
        float x0 = nh.x + (m[r][0] + 48.f * b3v.x) * (1.f / 30.f);
        float x1 = nh.y + (m[r][1] + 48.f * b3v.y) * (1.f / 30.f);
        float x2 = nh.z + (m[r][2] + 48.f * b3v.z) * (1.f / 30.f);
        float x3 = nh.w + (m[r][3] + 48.f * b3v.w) * (1.f / 30.f);
        float sum = x0 + x1 + x2 + x3;
        float sq = x0 * x0 + x1 * x1 + x2 * x2 + x3 * x3;
#pragma unroll
        for (int off = 16; off; off >>= 1) {
            sum += __shfl_xor_sync(0xffffffffu, sum, off);
            sq += __shfl_xor_sync(0xffffffffu, sq, off);
        }
        float mean = sum * (1.f / 128.f);
        float var = sq * (1.f / 128.f) - mean * mean;
        float rs = rsqrtf(var + 1e-5f);
        float4 u;
        u.x = (x0 - mean) * rs * gv.x + lv.x;
        u.y = (x1 - mean) * rs * gv.y + lv.y;
        u.z = (x2 - mean) * rs * gv.z + lv.z;
        u.w = (x3 - mean) * rs * gv.w + lv.w;
        *(float4*)(sU + rr * 128 + c0) = u;
    }
    CP_WAIT(0);
    __syncthreads();

    // phase 2: y = U @ Wu ; out = LN(nh + y + bu)
    float y[2][4];
#pragma unroll
    for (int r = 0; r < 2; r++)
#pragma unroll
        for (int j = 0; j < 4; j++) y[r][j] = 0.f;
#pragma unroll 4
    for (int k = 0; k < 128; k++) {
        float4 w = *(const float4*)(sWu + k * 128 + c0);
#pragma unroll
        for (int r = 0; r < 2; r++) {
            float u = sU[(warp * 2 + r) * 128 + k];
            y[r][0] += u * w.x; y[r][1] += u * w.y;
            y[r][2] += u * w.z; y[r][3] += u * w.w;
        }
    }
#pragma unroll
    for (int r = 0; r < 2; r++) {
        int rr = warp * 2 + r;
        float4 nh = *(const float4*)(sNH + rr * 128 + c0);
        float x0 = nh.x + y[r][0] + bv.x;
        float x1 = nh.y + y[r][1] + bv.y;
        float x2 = nh.z + y[r][2] + bv.z;
        float x3 = nh.w + y[r][3] + bv.w;
        float sum = x0 + x1 + x2 + x3;
        float sq = x0 * x0 + x1 * x1 + x2 * x2 + x3 * x3;
#pragma unroll
        for (int off = 16; off; off >>= 1) {
            sum += __shfl_xor_sync(0xffffffffu, sum, off);
            sq += __shfl_xor_sync(0xffffffffu, sq, off);
        }
        float mean = sum * (1.f / 128.f);
        float var = sq * (1.f / 128.f) - mean * mean;
        float rs = rsqrtf(var + 1e-5f);
        float4 o;
        o.x = (x0 - mean) * rs * gv.x + lv.x;
        o.y = (x1 - mean) * rs * gv.y + lv.y;
        o.z = (x2 - mean) * rs * gv.z + lv.z;
        o.w = (x3 - mean) * rs * gv.w + lv.w;
        *(float4*)(out + (size_t)(rbase + rr) * 128 + c0) = o;
    }
}

// ---------------- launch ----------------
extern "C" void kernel_launch(void* const* d_in, const int* in_sizes, int n_in,
                              void* d_out, int out_size) {
    const float* node_h = (const float*)d_in[0];
    const float* edge_h = (const float*)d_in[1];
    const void* edge_index = d_in[2];
    const float* W1 = (const float*)d_in[3];
    const float* b1 = (const float*)d_in[4];
    const float* W2 = (const float*)d_in[5];
    const float* b2 = (const float*)d_in[6];
    const float* W3 = (const float*)d_in[7];
    const float* b3 = (const float*)d_in[8];
    const float* Wu = (const float*)d_in[9];
    const float* bu = (const float*)d_in[10];
    const float* ln_g = (const float*)d_in[11];
    const float* ln_b = (const float*)d_in[12];
    float* out = (float*)d_out;

    cudaFuncSetAttribute(pij_kernel, cudaFuncAttributeMaxDynamicSharedMemorySize, 147456);
    cudaFuncSetAttribute(mlp_kernel, cudaFuncAttributeMaxDynamicSharedMemorySize, SMEM_MLP);
    cudaFuncSetAttribute(final_kernel, cudaFuncAttributeMaxDynamicSharedMemorySize, 180224);

    pre_kernel<<<2272, 256>>>((const float4*)edge_h, edge_index, W1, W2);
    pij_kernel<<<128, 256, 147456>>>(node_h, W1, b1);
    mlp_kernel<<<148, NTHR, SMEM_MLP>>>(b2);
    final_kernel<<<128, 512, 180224>>>(node_h, W3, b3, Wu, bu, ln_g, ln_b, out);
}

// round 12
// speedup vs baseline: 1.0025x; 1.0025x over previous
#include <cuda_runtime.h>
#include <cuda_bf16.h>
#include <stdint.h>

#define Bn 2
#define Nn 2048
#define Kn 48
#define Cn 128
#define TILES (Bn * Nn / 2)

// ---------------- device scratch ----------------
__device__ __nv_bfloat16 g_W1c[128 * 128];   // [n][k] = W1[256+k][n]
__device__ __nv_bfloat16 g_W2t[128 * 128];   // [n][k]
__device__ __nv_bfloat16 g_edge_bf[(size_t)Bn * Nn * Kn * Cn];  // 50 MB bf16 edges
__device__ float g_Pi[Bn * Nn * Cn];         // node_h @ W1[0:128] + b1
__device__ float g_Pj[Bn * Nn * Cn];         // node_h @ W1[128:256]
__device__ float g_sumh2[Bn * Nn * Cn];      // per-node sum of gelu(h2) over K edges
__device__ int   g_joff[Bn * Nn * Kn];       // precomputed gather row: b*Nn + j

// ---------------- helpers ----------------
__device__ __forceinline__ uint32_t smem_u32(const void* p) {
    uint32_t a;
    asm("{ .reg .u64 t; cvta.to.shared.u64 t, %1; cvt.u32.u64 %0, t; }" : "=r"(a) : "l"(p));
    return a;
}
__device__ __forceinline__ unsigned pk2(float a, float b) {
    __nv_bfloat162 t = __floats2bfloat162_rn(a, b);
    return *reinterpret_cast<unsigned*>(&t);
}
// tanh-GELU via Pade(5,4): tanh(y) ~ y(945+105y^2+y^4)/(945+420y^2+15y^4),
// clamp |y|<=3.68 (poly reaches 1.0 there; beyond, gelu -> x). 1 MUFU, ~15 ops.
__device__ __forceinline__ float gelu_fast(float x) {
    float y = x * fmaf(0.03567740814f, x * x, 0.79788456f);
    y = fminf(fmaxf(y, -3.68f), 3.68f);
    float y2 = y * y;
    float num = y * fmaf(y2, y2 + 105.0f, 945.0f);
    float den = fmaf(y2, fmaf(15.0f, y2, 420.0f), 945.0f);
    float r;
    asm("rcp.approx.ftz.f32 %0, %1;" : "=f"(r) : "f"(den));
    float hx = 0.5f * x;
    return fmaf(hx * num, r, hx);
}
__device__ __forceinline__ void mma16816(float c[4], const uint32_t a[4], const uint32_t b[2]) {
    asm volatile(
        "mma.sync.aligned.m16n8k16.row.col.f32.bf16.bf16.f32 "
        "{%0,%1,%2,%3},{%4,%5,%6,%7},{%8,%9},{%0,%1,%2,%3};"
        : "+f"(c[0]), "+f"(c[1]), "+f"(c[2]), "+f"(c[3])
        : "r"(a[0]), "r"(a[1]), "r"(a[2]), "r"(a[3]), "r"(b[0]), "r"(b[1]));
}
__device__ __forceinline__ void ldsm4(uint32_t r[4], uint32_t addr) {
    asm volatile("ldmatrix.sync.aligned.m8n8.x4.shared.b16 {%0,%1,%2,%3}, [%4];"
                 : "=r"(r[0]), "=r"(r[1]), "=r"(r[2]), "=r"(r[3]) : "r"(addr));
}
__device__ __forceinline__ void cp16(uint32_t dst, const void* src) {
    asm volatile("cp.async.cg.shared.global [%0], [%1], 16;" :: "r"(dst), "l"(src) : "memory");
}
#define CP_COMMIT() asm volatile("cp.async.commit_group;" ::: "memory")
#define CP_WAIT(N)  asm volatile("cp.async.wait_group %0;" :: "n"(N) : "memory")

// XOR-swizzled bf16 tile: 256B rows, 16B chunks; conflict-free ldmatrix, no padding
__device__ __forceinline__ uint32_t phys(int row, int chunk) {
    return (uint32_t)(row * 256 + ((chunk ^ (row & 7)) << 4));
}

// ---------------- pre: conv (edge fp32->bf16) + joff + weight transposes ----------------
__global__ void __launch_bounds__(256)
pre_kernel(const float4* __restrict__ src, const void* __restrict__ edge_index,
           const float* __restrict__ W1, const float* __restrict__ W2) {
    const int bx = blockIdx.x;
    if (bx < 2048) {
        const size_t total = (size_t)Bn * Nn * Kn * 32;   // float4 count
        const size_t step = (size_t)2048 * 256;
        for (size_t i = (size_t)bx * 256 + threadIdx.x; i < total; i += step) {
            float4 v = src[i];
            uint2 p;
            p.x = pk2(v.x, v.y);
            p.y = pk2(v.z, v.w);
            *(uint2*)(g_edge_bf + i * 4) = p;
        }
    } else if (bx < 2144) {
        const unsigned* w = (const unsigned*)edge_index;
        int is64 = 1;
#pragma unroll 1
        for (int t = 1; t < 128; t += 2)
            if (w[t] != 0u) { is64 = 0; break; }
        const long long* idx64 = (const long long*)edge_index;
        const int* idx32 = (const int*)edge_index;
        int base = (bx - 2048) * 2048 + threadIdx.x;
#pragma unroll
        for (int q = 0; q < 8; q++) {
            int e = base + q * 256;
            int j = is64 ? (int)idx64[e] : idx32[e];
            int b = e / (Nn * Kn);
            g_joff[e] = b * Nn + j;
        }
    } else {
        int i = (bx - 2144) * 256 + threadIdx.x;   // 0..32767
        if (i < 16384) {
            int n = i >> 7, k = i & 127;
            g_W1c[i] = __float2bfloat16_rn(W1[(256 + k) * 128 + n]);
        } else {
            int j = i - 16384, n = j >> 7, k = j & 127;
            g_W2t[j] = __float2bfloat16_rn(W2[k * 128 + n]);
        }
    }
}

// ---------------- Pi/Pj precompute (fp32, register-blocked) ----------------
__global__ void __launch_bounds__(256)
pij_kernel(const float* __restrict__ node_h, const float* __restrict__ W1,
           const float* __restrict__ b1) {
    extern __shared__ float sw[];           // Wa 16384 | Wb 16384 | X 4096
    float* sWa = sw;
    float* sWb = sw + 16384;
    float* sX  = sw + 32768;
    int tid = threadIdx.x, lane = tid & 31, warp = tid >> 5;
    for (int i = tid; i < 16384; i += 256) {
        sWa[i] = W1[i];
        sWb[i] = W1[16384 + i];
    }
    int rbase = blockIdx.x * 32;
    for (int i = tid; i < 4096; i += 256)
        sX[i] = node_h[(size_t)rbase * 128 + i];
    __syncthreads();

    int c0 = lane * 4;
    float yi[4][4], yj[4][4];
#pragma unroll
    for (int r = 0; r < 4; r++)
#pragma unroll
        for (int j = 0; j < 4; j++) { yi[r][j] = 0.f; yj[r][j] = 0.f; }

#pragma unroll 4
    for (int k = 0; k < 128; k++) {
        float4 wa = *(const float4*)(sWa + k * 128 + c0);
        float4 wb = *(const float4*)(sWb + k * 128 + c0);
#pragma unroll
        for (int r = 0; r < 4; r++) {
            float x = sX[(warp * 4 + r) * 128 + k];
            yi[r][0] += x * wa.x; yi[r][1] += x * wa.y;
            yi[r][2] += x * wa.z; yi[r][3] += x * wa.w;
            yj[r][0] += x * wb.x; yj[r][1] += x * wb.y;
            yj[r][2] += x * wb.z; yj[r][3] += x * wb.w;
        }
    }
    float4 bv = *(const float4*)(b1 + c0);
#pragma unroll
    for (int r = 0; r < 4; r++) {
        size_t row = (size_t)rbase + warp * 4 + r;
        float4 oi;
        oi.x = yi[r][0] + bv.x; oi.y = yi[r][1] + bv.y;
        oi.z = yi[r][2] + bv.z; oi.w = yi[r][3] + bv.w;
        *(float4*)(g_Pi + row * 128 + c0) = oi;
        float4 oj; oj.x = yj[r][0]; oj.y = yj[r][1]; oj.z = yj[r][2]; oj.w = yj[r][3];
        *(float4*)(g_Pj + row * 128 + c0) = oj;
    }
}

// ---------------- persistent edge-MLP kernel: L1+L2 only, sum(h2) out ----------------
#define OFF_E0  0
#define OFF_E1  24576
#define OFF_H   49152
#define OFF_PJ  73728          // 96 rows x 132 floats (528B rows) -> 50688
#define OFF_W1  124416
#define OFF_W2  157184
#define OFF_B2  189952
#define OFF_PI  190464         // 2 x 128 floats
#define SMEM_MLP 191488
#define NTHR 512

__global__ void __launch_bounds__(NTHR, 1)
mlp_kernel(const float* __restrict__ b2) {
    extern __shared__ char smem[];
    const uint32_t sb = smem_u32(smem);
    float* sPJ = (float*)(smem + OFF_PJ);
    float* sB2 = (float*)(smem + OFF_B2);
    float* sPi = (float*)(smem + OFF_PI);

    const int tid = threadIdx.x, lane = tid & 31, warp = tid >> 5;
    const int wm = warp >> 3;                 // 0/1 : node within tile
    const int wn = warp & 7;                  // 0..7 : 16-col group
    const int r0 = wm * 48;
    const int cq = (lane & 3) * 2;

    // stage weights (swizzled) + b2
    for (int i = tid; i < 128 * 16; i += NTHR) {
        int n = i >> 4, ch = (i & 15);
        uint32_t d = phys(n, ch);
        *(uint4*)(smem + OFF_W1 + d) = *(const uint4*)(g_W1c + n * 128 + ch * 8);
        *(uint4*)(smem + OFF_W2 + d) = *(const uint4*)(g_W2t + n * 128 + ch * 8);
    }
    if (tid < 128) sB2[tid] = b2[tid];

    auto issue_edges = [&](uint32_t ebuf, int tile) {
        size_t rbase = (size_t)tile * 96;
#pragma unroll 1
        for (int i = tid; i < 1536; i += NTHR) {
            int row = i >> 4, ch = i & 15;
            cp16(sb + ebuf + phys(row, ch), g_edge_bf + (rbase + row) * 128 + ch * 8);
        }
    };
    auto issue_pj = [&](int tile) {
        size_t ibase = (size_t)tile * 96;
#pragma unroll 1
        for (int i = tid; i < 3072; i += NTHR) {
            int row = i >> 5, ch = i & 31;
            int jr = g_joff[ibase + row];
            cp16(sb + OFF_PJ + row * 528 + ch * 16,
                 (const char*)g_Pj + ((size_t)jr << 9) + ch * 16);
        }
    };

    float acc[3][2][4];
    auto run_mma = [&](uint32_t aOff, uint32_t wOff) {
#pragma unroll
        for (int mt = 0; mt < 3; mt++)
#pragma unroll
            for (int nt = 0; nt < 2; nt++)
#pragma unroll
                for (int q = 0; q < 4; q++) acc[mt][nt][q] = 0.f;
#pragma unroll
        for (int kt = 0; kt < 8; kt++) {
            int ch = kt * 2 + (lane >> 4);
            uint32_t rb[4], ra0[4], ra1[4], ra2[4];
            ldsm4(rb,  sb + wOff + phys(wn * 16 + (lane & 15), ch));
            ldsm4(ra0, sb + aOff + phys(r0 + (lane & 15), ch));
            ldsm4(ra1, sb + aOff + phys(r0 + 16 + (lane & 15), ch));
            ldsm4(ra2, sb + aOff + phys(r0 + 32 + (lane & 15), ch));
#pragma unroll
            for (int h = 0; h < 2; h++) {
                uint32_t bbf[2] = { rb[h], rb[2 + h] };
                mma16816(acc[0][h], ra0, bbf);
                mma16816(acc[1][h], ra1, bbf);
                mma16816(acc[2][h], ra2, bbf);
            }
        }
    };

    // ---- initial prefetch: tile t0 ----
    int t = blockIdx.x;
    issue_edges(OFF_E0, t); CP_COMMIT();       // A(t0)
    issue_pj(t);            CP_COMMIT();       // B(t0)

    int it = 0;
#pragma unroll 1
    for (; t < TILES; t += gridDim.x, it++) {
        const uint32_t eCur = (it & 1) ? OFF_E1 : OFF_E0;
        const uint32_t eNxt = (it & 1) ? OFF_E0 : OFF_E1;
        const int g0 = t * 2;
        const int tn = t + gridDim.x;
        const bool hn = tn < TILES;

        // a: prefetch next edges; stage Pi rows for this tile
        if (hn) issue_edges(eNxt, tn);
        CP_COMMIT();                            // A(next)
        if (tid < 256) sPi[tid] = g_Pi[(size_t)g0 * 128 + tid];
        CP_WAIT(2);                             // edges(cur) ready
        __syncthreads();

        // b: layer 1 MMA (edge part)
        run_mma(eCur, OFF_W1);

        // c: PJ(cur) ready
        CP_WAIT(1);
        __syncthreads();

        // d: epi1 = gelu(acc + Pi + Pj) -> H
#pragma unroll
        for (int nt = 0; nt < 2; nt++) {
            int c = wn * 16 + nt * 8 + cq;
            float pix = sPi[wm * 128 + c], piy = sPi[wm * 128 + c + 1];
#pragma unroll
            for (int mt = 0; mt < 3; mt++) {
                int r = r0 + mt * 16 + (lane >> 2);
                float h00 = acc[mt][nt][0] + pix + sPJ[r * 132 + c];
                float h01 = acc[mt][nt][1] + piy + sPJ[r * 132 + c + 1];
                float h10 = acc[mt][nt][2] + pix + sPJ[(r + 8) * 132 + c];
                float h11 = acc[mt][nt][3] + piy + sPJ[(r + 8) * 132 + c + 1];
                uint32_t base = phys(r, c >> 3) + (c & 7) * 2;
                uint32_t base8 = phys(r + 8, c >> 3) + (c & 7) * 2;
                *(unsigned*)(smem + OFF_H + base)  = pk2(gelu_fast(h00), gelu_fast(h01));
                *(unsigned*)(smem + OFF_H + base8) = pk2(gelu_fast(h10), gelu_fast(h11));
            }
        }
        __syncthreads();

        // e: prefetch next PJ
        if (hn) issue_pj(tn);
        CP_COMMIT();                            // B(next)

        // f: layer 2 MMA + gelu + row-sum over 48 edges (linearity of W3!)
        run_mma(OFF_H, OFF_W2);
        float s0[2] = {0.f, 0.f}, s1[2] = {0.f, 0.f};
#pragma unroll
        for (int mt = 0; mt < 3; mt++) {
#pragma unroll
            for (int nt = 0; nt < 2; nt++) {
                int c = wn * 16 + nt * 8 + cq;
                float bb0 = sB2[c], bb1 = sB2[c + 1];
                s0[nt] += gelu_fast(acc[mt][nt][0] + bb0) + gelu_fast(acc[mt][nt][2] + bb0);
                s1[nt] += gelu_fast(acc[mt][nt][1] + bb1) + gelu_fast(acc[mt][nt][3] + bb1);
            }
        }
#pragma unroll
        for (int off = 4; off < 32; off <<= 1)
#pragma unroll
            for (int nt = 0; nt < 2; nt++) {
                s0[nt] += __shfl_xor_sync(0xffffffffu, s0[nt], off);
                s1[nt] += __shfl_xor_sync(0xffffffffu, s1[nt], off);
            }
        if (lane < 4) {
#pragma unroll
            for (int nt = 0; nt < 2; nt++) {
                int c = wn * 16 + nt * 8 + lane * 2;
                float2 v; v.x = s0[nt]; v.y = s1[nt];
                *(float2*)(g_sumh2 + (size_t)(g0 + wm) * 128 + c) = v;
            }
        }
        // loop-top barrier separates f's H reads from next epi1's H writes
    }
}

// ---------------- final: m = sumh2@W3; u = LN(nh + (m+48b3)/30); out = LN(nh + u@Wu + bu)
#define FIN_W3 0
#define FIN_WU 16384
#define FIN_S  32768
#define FIN_U  36864
#define FIN_NH 40960
__global__ void __launch_bounds__(512)
final_kernel(const float* __restrict__ node_h, const float* __restrict__ W3,
             const float* __restrict__ b3, const float* __restrict__ Wu,
             const float* __restrict__ bu, const float* __restrict__ ln_g,
             const float* __restrict__ ln_b, float* __restrict__ out) {
    extern __shared__ float sh[];
    const uint32_t sb = smem_u32(sh);
    float* sW3 = sh + FIN_W3;
    float* sWu = sh + FIN_WU;
    float* sS  = sh + FIN_S;
    float* sU  = sh + FIN_U;
    float* sNH = sh + FIN_NH;
    int tid = threadIdx.x, lane = tid & 31, warp = tid >> 5;
    int rbase = blockIdx.x * 32;

    // group A: W3 + S + NH (phase-1 inputs)
    for (int i = tid; i < 4096; i += 512)
        cp16(sb + (FIN_W3 + i * 4) * 4, W3 + i * 4);
    for (int i = tid; i < 1024; i += 512) {
        cp16(sb + (FIN_S + i * 4) * 4, g_sumh2 + (size_t)rbase * 128 + i * 4);
        cp16(sb + (FIN_NH + i * 4) * 4, node_h + (size_t)rbase * 128 + i * 4);
    }
    CP_COMMIT();
    // group B: Wu (phase-2 input, arrives under phase-1 compute)
    for (int i = tid; i < 4096; i += 512)
        cp16(sb + (FIN_WU + i * 4) * 4, Wu + i * 4);
    CP_COMMIT();

    int c0 = lane * 4;
    float4 gv = *(const float4*)(ln_g + c0);
    float4 lv = *(const float4*)(ln_b + c0);
    float4 b3v = *(const float4*)(b3 + c0);
    float4 bv  = *(const float4*)(bu + c0);

    CP_WAIT(1);
    __syncthreads();

    // phase 1: m = S @ W3 ; u = LN(nh + (m + 48 b3)/30) -> sU   (2 rows/warp)
    float m[2][4];
#pragma unroll
    for (int r = 0; r < 2; r++)
#pragma unroll
        for (int j = 0; j < 4; j++) m[r][j] = 0.f;
#pragma unroll 4
    for (int k = 0; k < 128; k++) {
        float4 w = *(const float4*)(sW3 + k * 128 + c0);
#pragma unroll
        for (int r = 0; r < 2; r++) {
            float s = sS[(warp * 2 + r) * 128 + k];
            m[r][0] += s * w.x; m[r][1] += s * w.y;
            m[r][2] += s * w.z; m[r][3] += s * w.w;
        }
    }
#pragma unroll
    for (int r = 0; r < 2; r++) {
        int rr = warp * 2 + r;
        float4 nh = *(const float4*)(sNH + rr * 128 + c0);
        float x0 = nh.x + (m[r][0] + 48.f * b3v.x) * (1.f / 30.f);
        float x1 = nh.y + (m[r][1] + 48.f * b3v.y) * (1.f / 30.f);
        float x2 = nh.z + (m[r][2] + 48.f * b3v.z) * (1.f / 30.f);
        float x3 = nh.w + (m[r][3] + 48.f * b3v.w) * (1.f / 30.f);
        float sum = x0 + x1 + x2 + x3;
        float sq = x0 * x0 + x1 * x1 + x2 * x2 + x3 * x3;
#pragma unroll
        for (int off = 16; off; off >>= 1) {
            sum += __shfl_xor_sync(0xffffffffu, sum, off);
            sq += __shfl_xor_sync(0xffffffffu, sq, off);
        }
        float mean = sum * (1.f / 128.f);
        float var = sq * (1.f / 128.f) - mean * mean;
        float rs = rsqrtf(var + 1e-5f);
        float4 u;
        u.x = (x0 - mean) * rs * gv.x + lv.x;
        u.y = (x1 - mean) * rs * gv.y + lv.y;
        u.z = (x2 - mean) * rs * gv.z + lv.z;
        u.w = (x3 - mean) * rs * gv.w + lv.w;
        *(float4*)(sU + rr * 128 + c0) = u;
    }
    CP_WAIT(0);
    __syncthreads();

    // phase 2: y = U @ Wu ; out = LN(nh + y + bu)
    float y[2][4];
#pragma unroll
    for (int r = 0; r < 2; r++)
#pragma unroll
        for (int j = 0; j < 4; j++) y[r][j] = 0.f;
#pragma unroll 4
    for (int k = 0; k < 128; k++) {
        float4 w = *(const float4*)(sWu + k * 128 + c0);
#pragma unroll
        for (int r = 0; r < 2; r++) {
            float u = sU[(warp * 2 + r) * 128 + k];
            y[r][0] += u * w.x; y[r][1] += u * w.y;
            y[r][2] += u * w.z; y[r][3] += u * w.w;
        }
    }
#pragma unroll
    for (int r = 0; r < 2; r++) {
        int rr = warp * 2 + r;
        float4 nh = *(const float4*)(sNH + rr * 128 + c0);
        float x0 = nh.x + y[r][0] + bv.x;
        float x1 = nh.y + y[r][1] + bv.y;
        float x2 = nh.z + y[r][2] + bv.z;
        float x3 = nh.w + y[r][3] + bv.w;
        float sum = x0 + x1 + x2 + x3;
        float sq = x0 * x0 + x1 * x1 + x2 * x2 + x3 * x3;
#pragma unroll
        for (int off = 16; off; off >>= 1) {
            sum += __shfl_xor_sync(0xffffffffu, sum, off);
            sq += __shfl_xor_sync(0xffffffffu, sq, off);
        }
        float mean = sum * (1.f / 128.f);
        float var = sq * (1.f / 128.f) - mean * mean;
        float rs = rsqrtf(var + 1e-5f);
        float4 o;
        o.x = (x0 - mean) * rs * gv.x + lv.x;
        o.y = (x1 - mean) * rs * gv.y + lv.y;
        o.z = (x2 - mean) * rs * gv.z + lv.z;
        o.w = (x3 - mean) * rs * gv.w + lv.w;
        *(float4*)(out + (size_t)(rbase + rr) * 128 + c0) = o;
    }
}

// ---------------- launch ----------------
extern "C" void kernel_launch(void* const* d_in, const int* in_sizes, int n_in,
                              void* d_out, int out_size) {
    const float* node_h = (const float*)d_in[0];
    const float* edge_h = (const float*)d_in[1];
    const void* edge_index = d_in[2];
    const float* W1 = (const float*)d_in[3];
    const float* b1 = (const float*)d_in[4];
    const float* W2 = (const float*)d_in[5];
    const float* b2 = (const float*)d_in[6];
    const float* W3 = (const float*)d_in[7];
    const float* b3 = (const float*)d_in[8];
    const float* Wu = (const float*)d_in[9];
    const float* bu = (const float*)d_in[10];
    const float* ln_g = (const float*)d_in[11];
    const float* ln_b = (const float*)d_in[12];
    float* out = (float*)d_out;

    cudaFuncSetAttribute(pij_kernel, cudaFuncAttributeMaxDynamicSharedMemorySize, 147456);
    cudaFuncSetAttribute(mlp_kernel, cudaFuncAttributeMaxDynamicSharedMemorySize, SMEM_MLP);
    cudaFuncSetAttribute(final_kernel, cudaFuncAttributeMaxDynamicSharedMemorySize, 180224);

    pre_kernel<<<2272, 256>>>((const float4*)edge_h, edge_index, W1, W2);
    pij_kernel<<<128, 256, 147456>>>(node_h, W1, b1);
    mlp_kernel<<<148, NTHR, SMEM_MLP>>>(b2);
    final_kernel<<<128, 512, 180224>>>(node_h, W3, b3, Wu, bu, ln_g, ln_b, out);
}

// round 13
// speedup vs baseline: 1.0069x; 1.0043x over previous
#include <cuda_runtime.h>
#include <cuda_bf16.h>
#include <stdint.h>

#define Bn 2
#define Nn 2048
#define Kn 48
#define Cn 128
#define TILES (Bn * Nn / 2)

// ---------------- device scratch ----------------
__device__ __nv_bfloat16 g_W1c[128 * 128];   // [n][k] = W1[256+k][n]
__device__ __nv_bfloat16 g_W2t[128 * 128];   // [n][k]
__device__ __nv_bfloat16 g_edge_bf[(size_t)Bn * Nn * Kn * Cn];  // 50 MB bf16 edges
__device__ float g_Pi[Bn * Nn * Cn];         // node_h @ W1[0:128] + b1
__device__ float g_Pj[Bn * Nn * Cn];         // node_h @ W1[128:256]
__device__ float g_sumh2[Bn * Nn * Cn];      // per-node sum of gelu(h2) over K edges
__device__ int   g_joff[Bn * Nn * Kn];       // precomputed gather row: b*Nn + j

// ---------------- helpers ----------------
__device__ __forceinline__ uint32_t smem_u32(const void* p) {
    uint32_t a;
    asm("{ .reg .u64 t; cvta.to.shared.u64 t, %1; cvt.u32.u64 %0, t; }" : "=r"(a) : "l"(p));
    return a;
}
__device__ __forceinline__ unsigned pk2(float a, float b) {
    __nv_bfloat162 t = __floats2bfloat162_rn(a, b);
    return *reinterpret_cast<unsigned*>(&t);
}
// tanh-GELU via Pade(5,4): tanh(y) ~ y(945+105y^2+y^4)/(945+420y^2+15y^4),
// clamp |y|<=3.68 (poly reaches 1.0 there; beyond, gelu -> x). 1 MUFU, ~15 ops.
__device__ __forceinline__ float gelu_fast(float x) {
    float y = x * fmaf(0.03567740814f, x * x, 0.79788456f);
    y = fminf(fmaxf(y, -3.68f), 3.68f);
    float y2 = y * y;
    float num = y * fmaf(y2, y2 + 105.0f, 945.0f);
    float den = fmaf(y2, fmaf(15.0f, y2, 420.0f), 945.0f);
    float r;
    asm("rcp.approx.ftz.f32 %0, %1;" : "=f"(r) : "f"(den));
    float hx = 0.5f * x;
    return fmaf(hx * num, r, hx);
}
__device__ __forceinline__ void mma16816(float c[4], const uint32_t a[4], const uint32_t b[2]) {
    asm volatile(
        "mma.sync.aligned.m16n8k16.row.col.f32.bf16.bf16.f32 "
        "{%0,%1,%2,%3},{%4,%5,%6,%7},{%8,%9},{%0,%1,%2,%3};"
        : "+f"(c[0]), "+f"(c[1]), "+f"(c[2]), "+f"(c[3])
        : "r"(a[0]), "r"(a[1]), "r"(a[2]), "r"(a[3]), "r"(b[0]), "r"(b[1]));
}
__device__ __forceinline__ void ldsm4(uint32_t r[4], uint32_t addr) {
    asm volatile("ldmatrix.sync.aligned.m8n8.x4.shared.b16 {%0,%1,%2,%3}, [%4];"
                 : "=r"(r[0]), "=r"(r[1]), "=r"(r[2]), "=r"(r[3]) : "r"(addr));
}
__device__ __forceinline__ void cp16(uint32_t dst, const void* src) {
    asm volatile("cp.async.cg.shared.global [%0], [%1], 16;" :: "r"(dst), "l"(src) : "memory");
}
#define CP_COMMIT() asm volatile("cp.async.commit_group;" ::: "memory")
#define CP_WAIT(N)  asm volatile("cp.async.wait_group %0;" :: "n"(N) : "memory")

// XOR-swizzled bf16 tile: 256B rows, 16B chunks; conflict-free ldmatrix, no padding
__device__ __forceinline__ uint32_t phys(int row, int chunk) {
    return (uint32_t)(row * 256 + ((chunk ^ (row & 7)) << 4));
}

// ---------------- pre: conv (edge fp32->bf16) + joff + weight transposes ----------------
__global__ void __launch_bounds__(256)
pre_kernel(const float4* __restrict__ src, const void* __restrict__ edge_index,
           const float* __restrict__ W1, const float* __restrict__ W2) {
    const int bx = blockIdx.x;
    if (bx < 2048) {
        const size_t total = (size_t)Bn * Nn * Kn * 32;   // float4 count
        const size_t step = (size_t)2048 * 256;
        for (size_t i = (size_t)bx * 256 + threadIdx.x; i < total; i += step) {
            float4 v = src[i];
            uint2 p;
            p.x = pk2(v.x, v.y);
            p.y = pk2(v.z, v.w);
            *(uint2*)(g_edge_bf + i * 4) = p;
        }
    } else if (bx < 2144) {
        const unsigned* w = (const unsigned*)edge_index;
        int is64 = 1;
#pragma unroll 1
        for (int t = 1; t < 128; t += 2)
            if (w[t] != 0u) { is64 = 0; break; }
        const long long* idx64 = (const long long*)edge_index;
        const int* idx32 = (const int*)edge_index;
        int base = (bx - 2048) * 2048 + threadIdx.x;
#pragma unroll
        for (int q = 0; q < 8; q++) {
            int e = base + q * 256;
            int j = is64 ? (int)idx64[e] : idx32[e];
            int b = e / (Nn * Kn);
            g_joff[e] = b * Nn + j;
        }
    } else {
        int i = (bx - 2144) * 256 + threadIdx.x;   // 0..32767
        if (i < 16384) {
            int n = i >> 7, k = i & 127;
            g_W1c[i] = __float2bfloat16_rn(W1[(256 + k) * 128 + n]);
        } else {
            int j = i - 16384, n = j >> 7, k = j & 127;
            g_W2t[j] = __float2bfloat16_rn(W2[k * 128 + n]);
        }
    }
}

// ---------------- Pi/Pj precompute (fp32, register-blocked) ----------------
__global__ void __launch_bounds__(256)
pij_kernel(const float* __restrict__ node_h, const float* __restrict__ W1,
           const float* __restrict__ b1) {
    extern __shared__ float sw[];           // Wa 16384 | Wb 16384 | X 4096
    float* sWa = sw;
    float* sWb = sw + 16384;
    float* sX  = sw + 32768;
    int tid = threadIdx.x, lane = tid & 31, warp = tid >> 5;
    for (int i = tid; i < 16384; i += 256) {
        sWa[i] = W1[i];
        sWb[i] = W1[16384 + i];
    }
    int rbase = blockIdx.x * 32;
    for (int i = tid; i < 4096; i += 256)
        sX[i] = node_h[(size_t)rbase * 128 + i];
    __syncthreads();

    int c0 = lane * 4;
    float yi[4][4], yj[4][4];
#pragma unroll
    for (int r = 0; r < 4; r++)
#pragma unroll
        for (int j = 0; j < 4; j++) { yi[r][j] = 0.f; yj[r][j] = 0.f; }

#pragma unroll 4
    for (int k = 0; k < 128; k++) {
        float4 wa = *(const float4*)(sWa + k * 128 + c0);
        float4 wb = *(const float4*)(sWb + k * 128 + c0);
#pragma unroll
        for (int r = 0; r < 4; r++) {
            float x = sX[(warp * 4 + r) * 128 + k];
            yi[r][0] += x * wa.x; yi[r][1] += x * wa.y;
            yi[r][2] += x * wa.z; yi[r][3] += x * wa.w;
            yj[r][0] += x * wb.x; yj[r][1] += x * wb.y;
            yj[r][2] += x * wb.z; yj[r][3] += x * wb.w;
        }
    }
    float4 bv = *(const float4*)(b1 + c0);
#pragma unroll
    for (int r = 0; r < 4; r++) {
        size_t row = (size_t)rbase + warp * 4 + r;
        float4 oi;
        oi.x = yi[r][0] + bv.x; oi.y = yi[r][1] + bv.y;
        oi.z = yi[r][2] + bv.z; oi.w = yi[r][3] + bv.w;
        *(float4*)(g_Pi + row * 128 + c0) = oi;
        float4 oj; oj.x = yj[r][0]; oj.y = yj[r][1]; oj.z = yj[r][2]; oj.w = yj[r][3];
        *(float4*)(g_Pj + row * 128 + c0) = oj;
    }
}

// ---------------- persistent edge-MLP kernel: L1+L2 only, sum(h2) out ----------------
#define OFF_E0  0
#define OFF_E1  24576
#define OFF_H   49152
#define OFF_PJ  73728          // 96 rows x 132 floats (528B rows) -> 50688
#define OFF_W1  124416
#define OFF_W2  157184
#define OFF_B2  189952
#define OFF_PI  190464         // 2 x 128 floats
#define SMEM_MLP 191488
#define NTHR 512

__global__ void __launch_bounds__(NTHR, 1)
mlp_kernel(const float* __restrict__ b2) {
    extern __shared__ char smem[];
    const uint32_t sb = smem_u32(smem);
    float* sPJ = (float*)(smem + OFF_PJ);
    float* sB2 = (float*)(smem + OFF_B2);
    float* sPi = (float*)(smem + OFF_PI);

    const int tid = threadIdx.x, lane = tid & 31, warp = tid >> 5;
    const int wm = warp >> 3;                 // 0/1 : node within tile
    const int wn = warp & 7;                  // 0..7 : 16-col group
    const int r0 = wm * 48;
    const int cq = (lane & 3) * 2;

    // stage weights (swizzled) + b2
    for (int i = tid; i < 128 * 16; i += NTHR) {
        int n = i >> 4, ch = (i & 15);
        uint32_t d = phys(n, ch);
        *(uint4*)(smem + OFF_W1 + d) = *(const uint4*)(g_W1c + n * 128 + ch * 8);
        *(uint4*)(smem + OFF_W2 + d) = *(const uint4*)(g_W2t + n * 128 + ch * 8);
    }
    if (tid < 128) sB2[tid] = b2[tid];

    auto issue_edges = [&](uint32_t ebuf, int tile) {
        size_t rbase = (size_t)tile * 96;
#pragma unroll 1
        for (int i = tid; i < 1536; i += NTHR) {
            int row = i >> 4, ch = i & 15;
            cp16(sb + ebuf + phys(row, ch), g_edge_bf + (rbase + row) * 128 + ch * 8);
        }
    };
    auto issue_pj = [&](int tile) {
        size_t ibase = (size_t)tile * 96;
#pragma unroll 1
        for (int i = tid; i < 3072; i += NTHR) {
            int row = i >> 5, ch = i & 31;
            int jr = g_joff[ibase + row];
            cp16(sb + OFF_PJ + row * 528 + ch * 16,
                 (const char*)g_Pj + ((size_t)jr << 9) + ch * 16);
        }
    };

    float acc[3][2][4];
    auto run_mma = [&](uint32_t aOff, uint32_t wOff) {
#pragma unroll
        for (int mt = 0; mt < 3; mt++)
#pragma unroll
            for (int nt = 0; nt < 2; nt++)
#pragma unroll
                for (int q = 0; q < 4; q++) acc[mt][nt][q] = 0.f;
#pragma unroll
        for (int kt = 0; kt < 8; kt++) {
            int ch = kt * 2 + (lane >> 4);
            uint32_t rb[4];
            ldsm4(rb, sb + wOff + phys(wn * 16 + (lane & 15), ch));
#pragma unroll
            for (int mt = 0; mt < 3; mt++) {
                uint32_t ra[4];
                ldsm4(ra, sb + aOff + phys(r0 + mt * 16 + (lane & 15), ch));
#pragma unroll
                for (int h = 0; h < 2; h++) {
                    uint32_t bbf[2] = { rb[h], rb[2 + h] };
                    mma16816(acc[mt][h], ra, bbf);
                }
            }
        }
    };

    // ---- initial prefetch: tile t0 ----
    int t = blockIdx.x;
    issue_edges(OFF_E0, t); CP_COMMIT();       // A(t0)
    issue_pj(t);            CP_COMMIT();       // B(t0)

    int it = 0;
#pragma unroll 1
    for (; t < TILES; t += gridDim.x, it++) {
        const uint32_t eCur = (it & 1) ? OFF_E1 : OFF_E0;
        const uint32_t eNxt = (it & 1) ? OFF_E0 : OFF_E1;
        const int g0 = t * 2;
        const int tn = t + gridDim.x;
        const bool hn = tn < TILES;

        // a: prefetch next edges; stage Pi rows for this tile
        if (hn) issue_edges(eNxt, tn);
        CP_COMMIT();                            // A(next)
        if (tid < 256) sPi[tid] = g_Pi[(size_t)g0 * 128 + tid];
        CP_WAIT(2);                             // edges(cur) ready
        __syncthreads();

        // b: layer 1 MMA (edge part)
        run_mma(eCur, OFF_W1);

        // c: PJ(cur) ready
        CP_WAIT(1);
        __syncthreads();

        // d: epi1 = gelu(acc + Pi + Pj) -> H
#pragma unroll
        for (int nt = 0; nt < 2; nt++) {
            int c = wn * 16 + nt * 8 + cq;
            float pix = sPi[wm * 128 + c], piy = sPi[wm * 128 + c + 1];
#pragma unroll
            for (int mt = 0; mt < 3; mt++) {
                int r = r0 + mt * 16 + (lane >> 2);
                float h00 = acc[mt][nt][0] + pix + sPJ[r * 132 + c];
                float h01 = acc[mt][nt][1] + piy + sPJ[r * 132 + c + 1];
                float h10 = acc[mt][nt][2] + pix + sPJ[(r + 8) * 132 + c];
                float h11 = acc[mt][nt][3] + piy + sPJ[(r + 8) * 132 + c + 1];
                uint32_t base = phys(r, c >> 3) + (c & 7) * 2;
                uint32_t base8 = phys(r + 8, c >> 3) + (c & 7) * 2;
                *(unsigned*)(smem + OFF_H + base)  = pk2(gelu_fast(h00), gelu_fast(h01));
                *(unsigned*)(smem + OFF_H + base8) = pk2(gelu_fast(h10), gelu_fast(h11));
            }
        }
        __syncthreads();

        // e: prefetch next PJ
        if (hn) issue_pj(tn);
        CP_COMMIT();                            // B(next)

        // f: layer 2 MMA + gelu + row-sum over 48 edges (linearity of W3!)
        run_mma(OFF_H, OFF_W2);
        float s0[2] = {0.f, 0.f}, s1[2] = {0.f, 0.f};
#pragma unroll
        for (int mt = 0; mt < 3; mt++) {
#pragma unroll
            for (int nt = 0; nt < 2; nt++) {
                int c = wn * 16 + nt * 8 + cq;
                float bb0 = sB2[c], bb1 = sB2[c + 1];
                s0[nt] += gelu_fast(acc[mt][nt][0] + bb0) + gelu_fast(acc[mt][nt][2] + bb0);
                s1[nt] += gelu_fast(acc[mt][nt][1] + bb1) + gelu_fast(acc[mt][nt][3] + bb1);
            }
        }
#pragma unroll
        for (int off = 4; off < 32; off <<= 1)
#pragma unroll
            for (int nt = 0; nt < 2; nt++) {
                s0[nt] += __shfl_xor_sync(0xffffffffu, s0[nt], off);
                s1[nt] += __shfl_xor_sync(0xffffffffu, s1[nt], off);
            }
        if (lane < 4) {
#pragma unroll
            for (int nt = 0; nt < 2; nt++) {
                int c = wn * 16 + nt * 8 + lane * 2;
                float2 v; v.x = s0[nt]; v.y = s1[nt];
                *(float2*)(g_sumh2 + (size_t)(g0 + wm) * 128 + c) = v;
            }
        }
        // loop-top barrier separates f's H reads from next epi1's H writes
    }
}

// ---------------- final: m = sumh2@W3; u = LN(nh + (m+48b3)/30); out = LN(nh + u@Wu + bu)
#define FIN_W3 0
#define FIN_WU 16384
#define FIN_S  32768
#define FIN_U  36864
#define FIN_NH 40960
__global__ void __launch_bounds__(512)
final_kernel(const float* __restrict__ node_h, const float* __restrict__ W3,
             const float* __restrict__ b3, const float* __restrict__ Wu,
             const float* __restrict__ bu, const float* __restrict__ ln_g,
             const float* __restrict__ ln_b, float* __restrict__ out) {
    extern __shared__ float sh[];
    const uint32_t sb = smem_u32(sh);
    float* sW3 = sh + FIN_W3;
    float* sWu = sh + FIN_WU;
    float* sS  = sh + FIN_S;
    float* sU  = sh + FIN_U;
    float* sNH = sh + FIN_NH;
    int tid = threadIdx.x, lane = tid & 31, warp = tid >> 5;
    int rbase = blockIdx.x * 32;

    // group A: W3 + S + NH (phase-1 inputs)
    for (int i = tid; i < 4096; i += 512)
        cp16(sb + (FIN_W3 + i * 4) * 4, W3 + i * 4);
    for (int i = tid; i < 1024; i += 512) {
        cp16(sb + (FIN_S + i * 4) * 4, g_sumh2 + (size_t)rbase * 128 + i * 4);
        cp16(sb + (FIN_NH + i * 4) * 4, node_h + (size_t)rbase * 128 + i * 4);
    }
    CP_COMMIT();
    // group B: Wu (phase-2 input, arrives under phase-1 compute)
    for (int i = tid; i < 4096; i += 512)
        cp16(sb + (FIN_WU + i * 4) * 4, Wu + i * 4);
    CP_COMMIT();

    int c0 = lane * 4;
    float4 gv = *(const float4*)(ln_g + c0);
    float4 lv = *(const float4*)(ln_b + c0);
    float4 b3v = *(const float4*)(b3 + c0);
    float4 bv  = *(const float4*)(bu + c0);

    CP_WAIT(1);
    __syncthreads();

    // phase 1: m = S @ W3 ; u = LN(nh + (m + 48 b3)/30) -> sU   (2 rows/warp)
    float m[2][4];
#pragma unroll
    for (int r = 0; r < 2; r++)
#pragma unroll
        for (int j = 0; j < 4; j++) m[r][j] = 0.f;
#pragma unroll 4
    for (int k = 0; k < 128; k++) {
        float4 w = *(const float4*)(sW3 + k * 128 + c0);
#pragma unroll
        for (int r = 0; r < 2; r++) {
            float s = sS[(warp * 2 + r) * 128 + k];
            m[r][0] += s * w.x; m[r][1] += s * w.y;
            m[r][2] += s * w.z; m[r][3] += s * w.w;
        }
    }
#pragma unroll
    for (int r = 0; r < 2; r++) {
        int rr = warp * 2 + r;
        float4 nh = *(const float4*)(sNH + rr * 128 + c0);
        float x0 = nh.x + (m[r][0] + 48.f * b3v.x) * (1.f / 30.f);
        float x1 = nh.y + (m[r][1] + 48.f * b3v.y) * (1.f / 30.f);
        float x2 = nh.z + (m[r][2] + 48.f * b3v.z) * (1.f / 30.f);
        float x3 = nh.w + (m[r][3] + 48.f * b3v.w) * (1.f / 30.f);
        float sum = x0 + x1 + x2 + x3;
        float sq = x0 * x0 + x1 * x1 + x2 * x2 + x3 * x3;
#pragma unroll
        for (int off = 16; off; off >>= 1) {
            sum += __shfl_xor_sync(0xffffffffu, sum, off);
            sq += __shfl_xor_sync(0xffffffffu, sq, off);
        }
        float mean = sum * (1.f / 128.f);
        float var = sq * (1.f / 128.f) - mean * mean;
        float rs = rsqrtf(var + 1e-5f);
        float4 u;
        u.x = (x0 - mean) * rs * gv.x + lv.x;
        u.y = (x1 - mean) * rs * gv.y + lv.y;
        u.z = (x2 - mean) * rs * gv.z + lv.z;
        u.w = (x3 - mean) * rs * gv.w + lv.w;
        *(float4*)(sU + rr * 128 + c0) = u;
    }
    CP_WAIT(0);
    __syncthreads();

    // phase 2: y = U @ Wu ; out = LN(nh + y + bu)
    float y[2][4];
#pragma unroll
    for (int r = 0; r < 2; r++)
#pragma unroll
        for (int j = 0; j < 4; j++) y[r][j] = 0.f;
#pragma unroll 4
    for (int k = 0; k < 128; k++) {
        float4 w = *(const float4*)(sWu + k * 128 + c0);
#pragma unroll
        for (int r = 0; r < 2; r++) {
            float u = sU[(warp * 2 + r) * 128 + k];
            y[r][0] += u * w.x; y[r][1] += u * w.y;
            y[r][2] += u * w.z; y[r][3] += u * w.w;
        }
    }
#pragma unroll
    for (int r = 0; r < 2; r++) {
        int rr = warp * 2 + r;
        float4 nh = *(const float4*)(sNH + rr * 128 + c0);
        float x0 = nh.x + y[r][0] + bv.x;
        float x1 = nh.y + y[r][1] + bv.y;
        float x2 = nh.z + y[r][2] + bv.z;
        float x3 = nh.w + y[r][3] + bv.w;
        float sum = x0 + x1 + x2 + x3;
        float sq = x0 * x0 + x1 * x1 + x2 * x2 + x3 * x3;
#pragma unroll
        for (int off = 16; off; off >>= 1) {
            sum += __shfl_xor_sync(0xffffffffu, sum, off);
            sq += __shfl_xor_sync(0xffffffffu, sq, off);
        }
        float mean = sum * (1.f / 128.f);
        float var = sq * (1.f / 128.f) - mean * mean;
        float rs = rsqrtf(var + 1e-5f);
        float4 o;
        o.x = (x0 - mean) * rs * gv.x + lv.x;
        o.y = (x1 - mean) * rs * gv.y + lv.y;
        o.z = (x2 - mean) * rs * gv.z + lv.z;
        o.w = (x3 - mean) * rs * gv.w + lv.w;
        *(float4*)(out + (size_t)(rbase + rr) * 128 + c0) = o;
    }
}

// ---------------- launch ----------------
extern "C" void kernel_launch(void* const* d_in, const int* in_sizes, int n_in,
                              void* d_out, int out_size) {
    const float* node_h = (const float*)d_in[0];
    const float* edge_h = (const float*)d_in[1];
    const void* edge_index = d_in[2];
    const float* W1 = (const float*)d_in[3];
    const float* b1 = (const float*)d_in[4];
    const float* W2 = (const float*)d_in[5];
    const float* b2 = (const float*)d_in[6];
    const float* W3 = (const float*)d_in[7];
    const float* b3 = (const float*)d_in[8];
    const float* Wu = (const float*)d_in[9];
    const float* bu = (const float*)d_in[10];
    const float* ln_g = (const float*)d_in[11];
    const float* ln_b = (const float*)d_in[12];
    float* out = (float*)d_out;

    cudaFuncSetAttribute(pij_kernel, cudaFuncAttributeMaxDynamicSharedMemorySize, 147456);
    cudaFuncSetAttribute(mlp_kernel, cudaFuncAttributeMaxDynamicSharedMemorySize, SMEM_MLP);
    cudaFuncSetAttribute(final_kernel, cudaFuncAttributeMaxDynamicSharedMemorySize, 180224);

    pre_kernel<<<2272, 256>>>((const float4*)edge_h, edge_index, W1, W2);
    pij_kernel<<<128, 256, 147456>>>(node_h, W1, b1);
    mlp_kernel<<<148, NTHR, SMEM_MLP>>>(b2);
    final_kernel<<<128, 512, 180224>>>(node_h, W3, b3, Wu, bu, ln_g, ln_b, out);
}

// round 14
// speedup vs baseline: 1.4335x; 1.4237x over previous
#include <cuda_runtime.h>
#include <cuda_bf16.h>
#include <stdint.h>

#define Bn 2
#define Nn 2048
#define Kn 48
#define Cn 128
#define TILES (Bn * Nn / 2)

// ---------------- device scratch ----------------
__device__ __nv_bfloat16 g_W1c[128 * 128];   // [n][k] = W1[256+k][n]
__device__ __nv_bfloat16 g_W2t[128 * 128];   // [n][k]
__device__ __nv_bfloat16 g_edge_bf[(size_t)Bn * Nn * Kn * Cn];  // 50 MB bf16 edges
__device__ float g_Pi[Bn * Nn * Cn];         // node_h @ W1[0:128] + b1
__device__ float g_Pj[Bn * Nn * Cn];         // node_h @ W1[128:256]
__device__ float g_sumh2[Bn * Nn * Cn];      // per-node sum of gelu(h2) over K edges
__device__ int   g_joff[Bn * Nn * Kn];       // precomputed gather row: b*Nn + j

// ---------------- helpers ----------------
__device__ __forceinline__ uint32_t smem_u32(const void* p) {
    uint32_t a;
    asm("{ .reg .u64 t; cvta.to.shared.u64 t, %1; cvt.u32.u64 %0, t; }" : "=r"(a) : "l"(p));
    return a;
}
__device__ __forceinline__ unsigned pk2(float a, float b) {
    __nv_bfloat162 t = __floats2bfloat162_rn(a, b);
    return *reinterpret_cast<unsigned*>(&t);
}
// tanh-GELU via Pade(5,4): tanh(y) ~ y(945+105y^2+y^4)/(945+420y^2+15y^4),
// clamp |y|<=3.68 (poly reaches 1.0 there; beyond, gelu -> x). 1 MUFU, ~15 ops.
__device__ __forceinline__ float gelu_fast(float x) {
    float y = x * fmaf(0.03567740814f, x * x, 0.79788456f);
    y = fminf(fmaxf(y, -3.68f), 3.68f);
    float y2 = y * y;
    float num = y * fmaf(y2, y2 + 105.0f, 945.0f);
    float den = fmaf(y2, fmaf(15.0f, y2, 420.0f), 945.0f);
    float r;
    asm("rcp.approx.ftz.f32 %0, %1;" : "=f"(r) : "f"(den));
    float hx = 0.5f * x;
    return fmaf(hx * num, r, hx);
}
__device__ __forceinline__ void mma16816(float c[4], const uint32_t a[4], const uint32_t b[2]) {
    asm volatile(
        "mma.sync.aligned.m16n8k16.row.col.f32.bf16.bf16.f32 "
        "{%0,%1,%2,%3},{%4,%5,%6,%7},{%8,%9},{%0,%1,%2,%3};"
        : "+f"(c[0]), "+f"(c[1]), "+f"(c[2]), "+f"(c[3])
        : "r"(a[0]), "r"(a[1]), "r"(a[2]), "r"(a[3]), "r"(b[0]), "r"(b[1]));
}
__device__ __forceinline__ void ldsm4(uint32_t r[4], uint32_t addr) {
    asm volatile("ldmatrix.sync.aligned.m8n8.x4.shared.b16 {%0,%1,%2,%3}, [%4];"
                 : "=r"(r[0]), "=r"(r[1]), "=r"(r[2]), "=r"(r[3]) : "r"(addr));
}
__device__ __forceinline__ void cp16(uint32_t dst, const void* src) {
    asm volatile("cp.async.cg.shared.global [%0], [%1], 16;" :: "r"(dst), "l"(src) : "memory");
}
#define CP_COMMIT() asm volatile("cp.async.commit_group;" ::: "memory")
#define CP_WAIT(N)  asm volatile("cp.async.wait_group %0;" :: "n"(N) : "memory")

// XOR-swizzled bf16 tile: 256B rows, 16B chunks; conflict-free ldmatrix, no padding
__device__ __forceinline__ uint32_t phys(int row, int chunk) {
    return (uint32_t)(row * 256 + ((chunk ^ (row & 7)) << 4));
}

// ---------------- pre: conv (edge fp32->bf16, wide) + joff + weight transposes ----------------
__global__ void __launch_bounds__(256)
pre_kernel(const float4* __restrict__ src, const void* __restrict__ edge_index,
           const float* __restrict__ W1, const float* __restrict__ W2) {
    const int bx = blockIdx.x;
    if (bx < 2048) {
        const size_t total = (size_t)Bn * Nn * Kn * 16;   // uint4 outputs
        const size_t step = (size_t)2048 * 256;
        for (size_t i = (size_t)bx * 256 + threadIdx.x; i < total; i += step) {
            float4 v0 = src[2 * i];
            float4 v1 = src[2 * i + 1];
            uint4 p;
            p.x = pk2(v0.x, v0.y); p.y = pk2(v0.z, v0.w);
            p.z = pk2(v1.x, v1.y); p.w = pk2(v1.z, v1.w);
            *(uint4*)(g_edge_bf + i * 8) = p;
        }
    } else if (bx < 2144) {
        const unsigned* w = (const unsigned*)edge_index;
        int is64 = 1;
#pragma unroll 1
        for (int t = 1; t < 128; t += 2)
            if (w[t] != 0u) { is64 = 0; break; }
        const long long* idx64 = (const long long*)edge_index;
        const int* idx32 = (const int*)edge_index;
        int base = (bx - 2048) * 2048 + threadIdx.x;
#pragma unroll
        for (int q = 0; q < 8; q++) {
            int e = base + q * 256;
            int j = is64 ? (int)idx64[e] : idx32[e];
            int b = e / (Nn * Kn);
            g_joff[e] = b * Nn + j;
        }
    } else {
        int i = (bx - 2144) * 256 + threadIdx.x;   // 0..32767
        if (i < 16384) {
            int n = i >> 7, k = i & 127;
            g_W1c[i] = __float2bfloat16_rn(W1[(256 + k) * 128 + n]);
        } else {
            int j = i - 16384, n = j >> 7, k = j & 127;
            g_W2t[j] = __float2bfloat16_rn(W2[k * 128 + n]);
        }
    }
}

// ---------------- Pi/Pj precompute (fp32, register-blocked) ----------------
__global__ void __launch_bounds__(256)
pij_kernel(const float* __restrict__ node_h, const float* __restrict__ W1,
           const float* __restrict__ b1) {
    extern __shared__ float sw[];           // Wa 16384 | Wb 16384 | X 4096
    float* sWa = sw;
    float* sWb = sw + 16384;
    float* sX  = sw + 32768;
    int tid = threadIdx.x, lane = tid & 31, warp = tid >> 5;
    for (int i = tid; i < 16384; i += 256) {
        sWa[i] = W1[i];
        sWb[i] = W1[16384 + i];
    }
    int rbase = blockIdx.x * 32;
    for (int i = tid; i < 4096; i += 256)
        sX[i] = node_h[(size_t)rbase * 128 + i];
    __syncthreads();

    int c0 = lane * 4;
    float yi[4][4], yj[4][4];
#pragma unroll
    for (int r = 0; r < 4; r++)
#pragma unroll
        for (int j = 0; j < 4; j++) { yi[r][j] = 0.f; yj[r][j] = 0.f; }

#pragma unroll 4
    for (int k = 0; k < 128; k++) {
        float4 wa = *(const float4*)(sWa + k * 128 + c0);
        float4 wb = *(const float4*)(sWb + k * 128 + c0);
#pragma unroll
        for (int r = 0; r < 4; r++) {
            float x = sX[(warp * 4 + r) * 128 + k];
            yi[r][0] += x * wa.x; yi[r][1] += x * wa.y;
            yi[r][2] += x * wa.z; yi[r][3] += x * wa.w;
            yj[r][0] += x * wb.x; yj[r][1] += x * wb.y;
            yj[r][2] += x * wb.z; yj[r][3] += x * wb.w;
        }
    }
    float4 bv = *(const float4*)(b1 + c0);
#pragma unroll
    for (int r = 0; r < 4; r++) {
        size_t row = (size_t)rbase + warp * 4 + r;
        float4 oi;
        oi.x = yi[r][0] + bv.x; oi.y = yi[r][1] + bv.y;
        oi.z = yi[r][2] + bv.z; oi.w = yi[r][3] + bv.w;
        *(float4*)(g_Pi + row * 128 + c0) = oi;
        float4 oj; oj.x = yj[r][0]; oj.y = yj[r][1]; oj.z = yj[r][2]; oj.w = yj[r][3];
        *(float4*)(g_Pj + row * 128 + c0) = oj;
    }
}

// ---------------- persistent edge-MLP kernel: L1+L2 only, sum(h2) out ----------------
#define OFF_E0  0
#define OFF_E1  24576
#define OFF_H   49152
#define OFF_PJ  73728          // 96 rows x 132 floats (528B rows) -> 50688
#define OFF_W1  124416
#define OFF_W2  157184
#define OFF_B2  189952
#define OFF_PI  190464         // 2 x 128 floats
#define SMEM_MLP 191488
#define NTHR 512

__global__ void __launch_bounds__(NTHR, 1)
mlp_kernel(const float* __restrict__ b2) {
    extern __shared__ char smem[];
    const uint32_t sb = smem_u32(smem);
    float* sPJ = (float*)(smem + OFF_PJ);
    float* sB2 = (float*)(smem + OFF_B2);
    float* sPi = (float*)(smem + OFF_PI);

    const int tid = threadIdx.x, lane = tid & 31, warp = tid >> 5;
    const int wm = warp >> 3;                 // 0/1 : node within tile
    const int wn = warp & 7;                  // 0..7 : 16-col group
    const int r0 = wm * 48;
    const int cq = (lane & 3) * 2;

    // stage weights (swizzled) + b2
    for (int i = tid; i < 128 * 16; i += NTHR) {
        int n = i >> 4, ch = (i & 15);
        uint32_t d = phys(n, ch);
        *(uint4*)(smem + OFF_W1 + d) = *(const uint4*)(g_W1c + n * 128 + ch * 8);
        *(uint4*)(smem + OFF_W2 + d) = *(const uint4*)(g_W2t + n * 128 + ch * 8);
    }
    if (tid < 128) sB2[tid] = b2[tid];

    auto issue_edges = [&](uint32_t ebuf, int tile) {
        size_t rbase = (size_t)tile * 96;
#pragma unroll 1
        for (int i = tid; i < 1536; i += NTHR) {
            int row = i >> 4, ch = i & 15;
            cp16(sb + ebuf + phys(row, ch), g_edge_bf + (rbase + row) * 128 + ch * 8);
        }
    };
    auto issue_pj = [&](int tile) {
        size_t ibase = (size_t)tile * 96;
#pragma unroll 1
        for (int i = tid; i < 3072; i += NTHR) {
            int row = i >> 5, ch = i & 31;
            int jr = g_joff[ibase + row];
            cp16(sb + OFF_PJ + row * 528 + ch * 16,
                 (const char*)g_Pj + ((size_t)jr << 9) + ch * 16);
        }
    };

    float acc[3][2][4];
    auto run_mma = [&](uint32_t aOff, uint32_t wOff) {
#pragma unroll
        for (int mt = 0; mt < 3; mt++)
#pragma unroll
            for (int nt = 0; nt < 2; nt++)
#pragma unroll
                for (int q = 0; q < 4; q++) acc[mt][nt][q] = 0.f;
#pragma unroll
        for (int kt = 0; kt < 8; kt++) {
            int ch = kt * 2 + (lane >> 4);
            uint32_t rb[4];
            ldsm4(rb, sb + wOff + phys(wn * 16 + (lane & 15), ch));
#pragma unroll
            for (int mt = 0; mt < 3; mt++) {
                uint32_t ra[4];
                ldsm4(ra, sb + aOff + phys(r0 + mt * 16 + (lane & 15), ch));
#pragma unroll
                for (int h = 0; h < 2; h++) {
                    uint32_t bbf[2] = { rb[h], rb[2 + h] };
                    mma16816(acc[mt][h], ra, bbf);
                }
            }
        }
    };

    // ---- initial prefetch: tile t0 ----
    int t = blockIdx.x;
    issue_edges(OFF_E0, t); CP_COMMIT();       // A(t0)
    issue_pj(t);            CP_COMMIT();       // B(t0)

    int it = 0;
#pragma unroll 1
    for (; t < TILES; t += gridDim.x, it++) {
        const uint32_t eCur = (it & 1) ? OFF_E1 : OFF_E0;
        const uint32_t eNxt = (it & 1) ? OFF_E0 : OFF_E1;
        const int g0 = t * 2;
        const int tn = t + gridDim.x;
        const bool hn = tn < TILES;

        // a: prefetch next edges; stage Pi rows for this tile
        if (hn) issue_edges(eNxt, tn);
        CP_COMMIT();                            // A(next)
        if (tid < 256) sPi[tid] = g_Pi[(size_t)g0 * 128 + tid];
        CP_WAIT(2);                             // edges(cur) ready
        __syncthreads();

        // b: layer 1 MMA (edge part)
        run_mma(eCur, OFF_W1);

        // c: PJ(cur) ready
        CP_WAIT(1);
        __syncthreads();

        // d: epi1 = gelu(acc + Pi + Pj) -> H
#pragma unroll
        for (int nt = 0; nt < 2; nt++) {
            int c = wn * 16 + nt * 8 + cq;
            float pix = sPi[wm * 128 + c], piy = sPi[wm * 128 + c + 1];
            const uint32_t cb = ((uint32_t)(c >> 3) << 4) | (uint32_t)((c & 7) * 2);
#pragma unroll
            for (int mt = 0; mt < 3; mt++) {
                int r = r0 + mt * 16 + (lane >> 2);
                float h00 = acc[mt][nt][0] + pix + sPJ[r * 132 + c];
                float h01 = acc[mt][nt][1] + piy + sPJ[r * 132 + c + 1];
                float h10 = acc[mt][nt][2] + pix + sPJ[(r + 8) * 132 + c];
                float h11 = acc[mt][nt][3] + piy + sPJ[(r + 8) * 132 + c + 1];
                uint32_t base  = (uint32_t)(r * 256) + (cb ^ ((uint32_t)(r & 7) << 4));
                uint32_t base8 = base + 2048;   // (r+8): same swizzle bits, +8 rows
                *(unsigned*)(smem + OFF_H + base)  = pk2(gelu_fast(h00), gelu_fast(h01));
                *(unsigned*)(smem + OFF_H + base8) = pk2(gelu_fast(h10), gelu_fast(h11));
            }
        }
        __syncthreads();

        // e: prefetch next PJ
        if (hn) issue_pj(tn);
        CP_COMMIT();                            // B(next)

        // f: layer 2 MMA + gelu + row-sum over 48 edges (linearity of W3!)
        run_mma(OFF_H, OFF_W2);
        float s0[2] = {0.f, 0.f}, s1[2] = {0.f, 0.f};
#pragma unroll
        for (int mt = 0; mt < 3; mt++) {
#pragma unroll
            for (int nt = 0; nt < 2; nt++) {
                int c = wn * 16 + nt * 8 + cq;
                float bb0 = sB2[c], bb1 = sB2[c + 1];
                s0[nt] += gelu_fast(acc[mt][nt][0] + bb0) + gelu_fast(acc[mt][nt][2] + bb0);
                s1[nt] += gelu_fast(acc[mt][nt][1] + bb1) + gelu_fast(acc[mt][nt][3] + bb1);
            }
        }
#pragma unroll
        for (int off = 4; off < 32; off <<= 1)
#pragma unroll
            for (int nt = 0; nt < 2; nt++) {
                s0[nt] += __shfl_xor_sync(0xffffffffu, s0[nt], off);
                s1[nt] += __shfl_xor_sync(0xffffffffu, s1[nt], off);
            }
        if (lane < 4) {
#pragma unroll
            for (int nt = 0; nt < 2; nt++) {
                int c = wn * 16 + nt * 8 + lane * 2;
                float2 v; v.x = s0[nt]; v.y = s1[nt];
                *(float2*)(g_sumh2 + (size_t)(g0 + wm) * 128 + c) = v;
            }
        }
        // loop-top barrier separates f's H reads from next epi1's H writes
    }
}

// ---------------- final: m = sumh2@W3; u = LN(nh + (m+48b3)/30); out = LN(nh + u@Wu + bu)
#define FIN_W3 0
#define FIN_WU 16384
#define FIN_S  32768
#define FIN_U  36864
#define FIN_NH 40960
__global__ void __launch_bounds__(512)
final_kernel(const float* __restrict__ node_h, const float* __restrict__ W3,
             const float* __restrict__ b3, const float* __restrict__ Wu,
             const float* __restrict__ bu, const float* __restrict__ ln_g,
             const float* __restrict__ ln_b, float* __restrict__ out) {
    extern __shared__ float sh[];
    const uint32_t sb = smem_u32(sh);
    float* sW3 = sh + FIN_W3;
    float* sWu = sh + FIN_WU;
    float* sS  = sh + FIN_S;
    float* sU  = sh + FIN_U;
    float* sNH = sh + FIN_NH;
    int tid = threadIdx.x, lane = tid & 31, warp = tid >> 5;
    int rbase = blockIdx.x * 32;

    // group A: W3 + S + NH (phase-1 inputs)
    for (int i = tid; i < 4096; i += 512)
        cp16(sb + (FIN_W3 + i * 4) * 4, W3 + i * 4);
    for (int i = tid; i < 1024; i += 512) {
        cp16(sb + (FIN_S + i * 4) * 4, g_sumh2 + (size_t)rbase * 128 + i * 4);
        cp16(sb + (FIN_NH + i * 4) * 4, node_h + (size_t)rbase * 128 + i * 4);
    }
    CP_COMMIT();
    // group B: Wu (phase-2 input, arrives under phase-1 compute)
    for (int i = tid; i < 4096; i += 512)
        cp16(sb + (FIN_WU + i * 4) * 4, Wu + i * 4);
    CP_COMMIT();

    int c0 = lane * 4;
    float4 gv = *(const float4*)(ln_g + c0);
    float4 lv = *(const float4*)(ln_b + c0);
    float4 b3v = *(const float4*)(b3 + c0);
    float4 bv  = *(const float4*)(bu + c0);

    CP_WAIT(1);
    __syncthreads();

    // phase 1: m = S @ W3 ; u = LN(nh + (m + 48 b3)/30) -> sU   (2 rows/warp)
    float m[2][4];
#pragma unroll
    for (int r = 0; r < 2; r++)
#pragma unroll
        for (int j = 0; j < 4; j++) m[r][j] = 0.f;
#pragma unroll 4
    for (int k = 0; k < 128; k++) {
        float4 w = *(const float4*)(sW3 + k * 128 + c0);
#pragma unroll
        for (int r = 0; r < 2; r++) {
            float s = sS[(warp * 2 + r) * 128 + k];
            m[r][0] += s * w.x; m[r][1] += s * w.y;
            m[r][2] += s * w.z; m[r][3] += s * w.w;
        }
    }
#pragma unroll
    for (int r = 0; r < 2; r++) {
        int rr = warp * 2 + r;
        float4 nh = *(const float4*)(sNH + rr * 128 + c0);
        float x0 = nh.x + (m[r][0] + 48.f * b3v.x) * (1.f / 30.f);
        float x1 = nh.y + (m[r][1] + 48.f * b3v.y) * (1.f / 30.f);
        float x2 = nh.z + (m[r][2] + 48.f * b3v.z) * (1.f / 30.f);
        float x3 = nh.w + (m[r][3] + 48.f * b3v.w) * (1.f / 30.f);
        float sum = x0 + x1 + x2 + x3;
        float sq = x0 * x0 + x1 * x1 + x2 * x2 + x3 * x3;
#pragma unroll
        for (int off = 16; off; off >>= 1) {
            sum += __shfl_xor_sync(0xffffffffu, sum, off);
            sq += __shfl_xor_sync(0xffffffffu, sq, off);
        }
        float mean = sum * (1.f / 128.f);
        float var = sq * (1.f / 128.f) - mean * mean;
        float rs = rsqrtf(var + 1e-5f);
        float4 u;
        u.x = (x0 - mean) * rs * gv.x + lv.x;
        u.y = (x1 - mean) * rs * gv.y + lv.y;
        u.z = (x2 - mean) * rs * gv.z + lv.z;
        u.w = (x3 - mean) * rs * gv.w + lv.w;
        *(float4*)(sU + rr * 128 + c0) = u;
    }
    CP_WAIT(0);
    __syncthreads();

    // phase 2: y = U @ Wu ; out = LN(nh + y + bu)
    float y[2][4];
#pragma unroll
    for (int r = 0; r < 2; r++)
#pragma unroll
        for (int j = 0; j < 4; j++) y[r][j] = 0.f;
#pragma unroll 4
    for (int k = 0; k < 128; k++) {
        float4 w = *(const float4*)(sWu + k * 128 + c0);
#pragma unroll
        for (int r = 0; r < 2; r++) {
            float u = sU[(warp * 2 + r) * 128 + k];
            y[r][0] += u * w.x; y[r][1] += u * w.y;
            y[r][2] += u * w.z; y[r][3] += u * w.w;
        }
    }
#pragma unroll
    for (int r = 0; r < 2; r++) {
        int rr = warp * 2 + r;
        float4 nh = *(const float4*)(sNH + rr * 128 + c0);
        float x0 = nh.x + y[r][0] + bv.x;
        float x1 = nh.y + y[r][1] + bv.y;
        float x2 = nh.z + y[r][2] + bv.z;
        float x3 = nh.w + y[r][3] + bv.w;
        float sum = x0 + x1 + x2 + x3;
        float sq = x0 * x0 + x1 * x1 + x2 * x2 + x3 * x3;
#pragma unroll
        for (int off = 16; off; off >>= 1) {
            sum += __shfl_xor_sync(0xffffffffu, sum, off);
            sq += __shfl_xor_sync(0xffffffffu, sq, off);
        }
        float mean = sum * (1.f / 128.f);
        float var = sq * (1.f / 128.f) - mean * mean;
        float rs = rsqrtf(var + 1e-5f);
        float4 o;
        o.x = (x0 - mean) * rs * gv.x + lv.x;
        o.y = (x1 - mean) * rs * gv.y + lv.y;
        o.z = (x2 - mean) * rs * gv.z + lv.z;
        o.w = (x3 - mean) * rs * gv.w + lv.w;
        *(float4*)(out + (size_t)(rbase + rr) * 128 + c0) = o;
    }
}

// ---------------- launch ----------------
extern "C" void kernel_launch(void* const* d_in, const int* in_sizes, int n_in,
                              void* d_out, int out_size) {
    const float* node_h = (const float*)d_in[0];
    const float* edge_h = (const float*)d_in[1];
    const void* edge_index = d_in[2];
    const float* W1 = (const float*)d_in[3];
    const float* b1 = (const float*)d_in[4];
    const float* W2 = (const float*)d_in[5];
    const float* b2 = (const float*)d_in[6];
    const float* W3 = (const float*)d_in[7];
    const float* b3 = (const float*)d_in[8];
    const float* Wu = (const float*)d_in[9];
    const float* bu = (const float*)d_in[10];
    const float* ln_g = (const float*)d_in[11];
    const float* ln_b = (const float*)d_in[12];
    float* out = (float*)d_out;

    cudaFuncSetAttribute(pij_kernel, cudaFuncAttributeMaxDynamicSharedMemorySize, 147456);
    cudaFuncSetAttribute(mlp_kernel, cudaFuncAttributeMaxDynamicSharedMemorySize, SMEM_MLP);
    cudaFuncSetAttribute(final_kernel, cudaFuncAttributeMaxDynamicSharedMemorySize, 180224);

    pre_kernel<<<2272, 256>>>((const float4*)edge_h, edge_index, W1, W2);
    pij_kernel<<<128, 256, 147456>>>(node_h, W1, b1);
    mlp_kernel<<<148, NTHR, SMEM_MLP>>>(b2);
    final_kernel<<<128, 512, 180224>>>(node_h, W3, b3, Wu, bu, ln_g, ln_b, out);
}

// round 15
// speedup vs baseline: 1.5961x; 1.1134x over previous
#include <cuda_runtime.h>
#include <cuda_bf16.h>
#include <stdint.h>

#define Bn 2
#define Nn 2048
#define Kn 48
#define Cn 128
#define TILES (Bn * Nn / 2)

// ---------------- device scratch ----------------
__device__ __nv_bfloat16 g_W1c[128 * 128];   // [n][k] = W1[256+k][n]
__device__ __nv_bfloat16 g_W2t[128 * 128];   // [n][k]
__device__ float g_Pi[Bn * Nn * Cn];         // node_h @ W1[0:128] + b1
__device__ float g_Pj[Bn * Nn * Cn];         // node_h @ W1[128:256]
__device__ float g_sumh2[Bn * Nn * Cn];      // per-node sum of gelu(h2) over K edges
__device__ int   g_joff[Bn * Nn * Kn];       // precomputed gather row: b*Nn + j

// ---------------- helpers ----------------
__device__ __forceinline__ uint32_t smem_u32(const void* p) {
    uint32_t a;
    asm("{ .reg .u64 t; cvta.to.shared.u64 t, %1; cvt.u32.u64 %0, t; }" : "=r"(a) : "l"(p));
    return a;
}
__device__ __forceinline__ unsigned pk2(float a, float b) {
    __nv_bfloat162 t = __floats2bfloat162_rn(a, b);
    return *reinterpret_cast<unsigned*>(&t);
}
// tanh-GELU via Pade(5,4): tanh(y) ~ y(945+105y^2+y^4)/(945+420y^2+15y^4),
// clamp |y|<=3.68 (poly reaches 1.0 there; beyond, gelu -> x). 1 MUFU, ~15 ops.
__device__ __forceinline__ float gelu_fast(float x) {
    float y = x * fmaf(0.03567740814f, x * x, 0.79788456f);
    y = fminf(fmaxf(y, -3.68f), 3.68f);
    float y2 = y * y;
    float num = y * fmaf(y2, y2 + 105.0f, 945.0f);
    float den = fmaf(y2, fmaf(15.0f, y2, 420.0f), 945.0f);
    float r;
    asm("rcp.approx.ftz.f32 %0, %1;" : "=f"(r) : "f"(den));
    float hx = 0.5f * x;
    return fmaf(hx * num, r, hx);
}
__device__ __forceinline__ void mma16816(float c[4], const uint32_t a[4], const uint32_t b[2]) {
    asm volatile(
        "mma.sync.aligned.m16n8k16.row.col.f32.bf16.bf16.f32 "
        "{%0,%1,%2,%3},{%4,%5,%6,%7},{%8,%9},{%0,%1,%2,%3};"
        : "+f"(c[0]), "+f"(c[1]), "+f"(c[2]), "+f"(c[3])
        : "r"(a[0]), "r"(a[1]), "r"(a[2]), "r"(a[3]), "r"(b[0]), "r"(b[1]));
}
__device__ __forceinline__ void ldsm4(uint32_t r[4], uint32_t addr) {
    asm volatile("ldmatrix.sync.aligned.m8n8.x4.shared.b16 {%0,%1,%2,%3}, [%4];"
                 : "=r"(r[0]), "=r"(r[1]), "=r"(r[2]), "=r"(r[3]) : "r"(addr));
}
__device__ __forceinline__ void cp16(uint32_t dst, const void* src) {
    asm volatile("cp.async.cg.shared.global [%0], [%1], 16;" :: "r"(dst), "l"(src) : "memory");
}
#define CP_COMMIT() asm volatile("cp.async.commit_group;" ::: "memory")
#define CP_WAIT(N)  asm volatile("cp.async.wait_group %0;" :: "n"(N) : "memory")

// XOR-swizzled bf16 tile: 256B rows, 16B chunks; conflict-free ldmatrix, no padding
__device__ __forceinline__ uint32_t phys(int row, int chunk) {
    return (uint32_t)(row * 256 + ((chunk ^ (row & 7)) << 4));
}

// ---------------- pre: joff + weight transposes (conv pass eliminated) ----------------
__global__ void __launch_bounds__(256)
pre_kernel(const void* __restrict__ edge_index,
           const float* __restrict__ W1, const float* __restrict__ W2) {
    const int bx = blockIdx.x;
    if (bx < 96) {
        const unsigned* w = (const unsigned*)edge_index;
        int is64 = 1;
#pragma unroll 1
        for (int t = 1; t < 128; t += 2)
            if (w[t] != 0u) { is64 = 0; break; }
        const long long* idx64 = (const long long*)edge_index;
        const int* idx32 = (const int*)edge_index;
        int base = bx * 2048 + threadIdx.x;
#pragma unroll
        for (int q = 0; q < 8; q++) {
            int e = base + q * 256;
            int j = is64 ? (int)idx64[e] : idx32[e];
            int b = e / (Nn * Kn);
            g_joff[e] = b * Nn + j;
        }
    } else {
        int i = (bx - 96) * 256 + threadIdx.x;   // 0..32767
        if (i < 16384) {
            int n = i >> 7, k = i & 127;
            g_W1c[i] = __float2bfloat16_rn(W1[(256 + k) * 128 + n]);
        } else {
            int j = i - 16384, n = j >> 7, k = j & 127;
            g_W2t[j] = __float2bfloat16_rn(W2[k * 128 + n]);
        }
    }
}

// ---------------- Pi/Pj precompute (fp32, register-blocked) ----------------
__global__ void __launch_bounds__(256)
pij_kernel(const float* __restrict__ node_h, const float* __restrict__ W1,
           const float* __restrict__ b1) {
    extern __shared__ float sw[];           // Wa 16384 | Wb 16384 | X 4096
    float* sWa = sw;
    float* sWb = sw + 16384;
    float* sX  = sw + 32768;
    int tid = threadIdx.x, lane = tid & 31, warp = tid >> 5;
    for (int i = tid; i < 16384; i += 256) {
        sWa[i] = W1[i];
        sWb[i] = W1[16384 + i];
    }
    int rbase = blockIdx.x * 32;
    for (int i = tid; i < 4096; i += 256)
        sX[i] = node_h[(size_t)rbase * 128 + i];
    __syncthreads();

    int c0 = lane * 4;
    float yi[4][4], yj[4][4];
#pragma unroll
    for (int r = 0; r < 4; r++)
#pragma unroll
        for (int j = 0; j < 4; j++) { yi[r][j] = 0.f; yj[r][j] = 0.f; }

#pragma unroll 4
    for (int k = 0; k < 128; k++) {
        float4 wa = *(const float4*)(sWa + k * 128 + c0);
        float4 wb = *(const float4*)(sWb + k * 128 + c0);
#pragma unroll
        for (int r = 0; r < 4; r++) {
            float x = sX[(warp * 4 + r) * 128 + k];
            yi[r][0] += x * wa.x; yi[r][1] += x * wa.y;
            yi[r][2] += x * wa.z; yi[r][3] += x * wa.w;
            yj[r][0] += x * wb.x; yj[r][1] += x * wb.y;
            yj[r][2] += x * wb.z; yj[r][3] += x * wb.w;
        }
    }
    float4 bv = *(const float4*)(b1 + c0);
#pragma unroll
    for (int r = 0; r < 4; r++) {
        size_t row = (size_t)rbase + warp * 4 + r;
        float4 oi;
        oi.x = yi[r][0] + bv.x; oi.y = yi[r][1] + bv.y;
        oi.z = yi[r][2] + bv.z; oi.w = yi[r][3] + bv.w;
        *(float4*)(g_Pi + row * 128 + c0) = oi;
        float4 oj; oj.x = yj[r][0]; oj.y = yj[r][1]; oj.z = yj[r][2]; oj.w = yj[r][3];
        *(float4*)(g_Pj + row * 128 + c0) = oj;
    }
}

// ---------------- persistent edge-MLP kernel: fused fp32-edge load/convert ----------------
#define OFF_E   0              // single edge buffer, 24576
#define OFF_H   24576
#define OFF_PJ  49152          // 96 rows x 132 floats (528B rows) -> 50688
#define OFF_W1  99840
#define OFF_W2  132608
#define OFF_B2  165376
#define OFF_PI  165888         // 2 x 128 floats
#define SMEM_MLP 166912
#define NTHR 512

__global__ void __launch_bounds__(NTHR, 1)
mlp_kernel(const float* __restrict__ edge_h, const float* __restrict__ b2) {
    extern __shared__ char smem[];
    const uint32_t sb = smem_u32(smem);
    float* sPJ = (float*)(smem + OFF_PJ);
    float* sB2 = (float*)(smem + OFF_B2);
    float* sPi = (float*)(smem + OFF_PI);

    const int tid = threadIdx.x, lane = tid & 31, warp = tid >> 5;
    const int wm = warp >> 3;                 // 0/1 : node within tile
    const int wn = warp & 7;                  // 0..7 : 16-col group
    const int r0 = wm * 48;
    const int cq = (lane & 3) * 2;

    // stage weights (swizzled) + b2
    for (int i = tid; i < 128 * 16; i += NTHR) {
        int n = i >> 4, ch = (i & 15);
        uint32_t d = phys(n, ch);
        *(uint4*)(smem + OFF_W1 + d) = *(const uint4*)(g_W1c + n * 128 + ch * 8);
        *(uint4*)(smem + OFF_W2 + d) = *(const uint4*)(g_W2t + n * 128 + ch * 8);
    }
    if (tid < 128) sB2[tid] = b2[tid];

    auto issue_pj = [&](int tile) {
        size_t ibase = (size_t)tile * 96;
#pragma unroll 1
        for (int i = tid; i < 3072; i += NTHR) {
            int row = i >> 5, ch = i & 31;
            int jr = g_joff[ibase + row];
            cp16(sb + OFF_PJ + row * 528 + ch * 16,
                 (const char*)g_Pj + ((size_t)jr << 9) + ch * 16);
        }
    };

    float acc[3][2][4];
    auto run_mma = [&](uint32_t aOff, uint32_t wOff) {
#pragma unroll
        for (int mt = 0; mt < 3; mt++)
#pragma unroll
            for (int nt = 0; nt < 2; nt++)
#pragma unroll
                for (int q = 0; q < 4; q++) acc[mt][nt][q] = 0.f;
#pragma unroll
        for (int kt = 0; kt < 8; kt++) {
            int ch = kt * 2 + (lane >> 4);
            uint32_t rb[4];
            ldsm4(rb, sb + wOff + phys(wn * 16 + (lane & 15), ch));
#pragma unroll
            for (int mt = 0; mt < 3; mt++) {
                uint32_t ra[4];
                ldsm4(ra, sb + aOff + phys(r0 + mt * 16 + (lane & 15), ch));
#pragma unroll
                for (int h = 0; h < 2; h++) {
                    uint32_t bbf[2] = { rb[h], rb[2 + h] };
                    mma16816(acc[mt][h], ra, bbf);
                }
            }
        }
    };

    // ---- initial PJ prefetch for tile t0 ----
    int t = blockIdx.x;
    issue_pj(t); CP_COMMIT();

#pragma unroll 1
    for (; t < TILES; t += gridDim.x) {
        const int g0 = t * 2;
        const int tn = t + gridDim.x;
        const bool hn = tn < TILES;

        // a: build edge tile — fp32 LDG batch, convert, STS swizzled; stage Pi
        {
            const float* ebase = edge_h + (size_t)t * 12288;
            float4 v[6];
#pragma unroll
            for (int q = 0; q < 3; q++) {
                int ci = tid + 512 * q;
                const float4* s = (const float4*)(ebase + (ci >> 4) * 128 + (ci & 15) * 8);
                v[2 * q] = s[0];
                v[2 * q + 1] = s[1];
            }
            if (tid < 256) sPi[tid] = g_Pi[(size_t)g0 * 128 + tid];
#pragma unroll
            for (int q = 0; q < 3; q++) {
                int ci = tid + 512 * q;
                uint4 p;
                p.x = pk2(v[2 * q].x, v[2 * q].y);
                p.y = pk2(v[2 * q].z, v[2 * q].w);
                p.z = pk2(v[2 * q + 1].x, v[2 * q + 1].y);
                p.w = pk2(v[2 * q + 1].z, v[2 * q + 1].w);
                *(uint4*)(smem + OFF_E + phys(ci >> 4, ci & 15)) = p;
            }
        }
        __syncthreads();

        // b: layer 1 MMA (edge part)
        run_mma(OFF_E, OFF_W1);

        // c: PJ(cur) ready
        CP_WAIT(0);
        __syncthreads();

        // d: epi1 = gelu(acc + Pi + Pj) -> H
#pragma unroll
        for (int nt = 0; nt < 2; nt++) {
            int c = wn * 16 + nt * 8 + cq;
            float pix = sPi[wm * 128 + c], piy = sPi[wm * 128 + c + 1];
            const uint32_t cb = ((uint32_t)(c >> 3) << 4) | (uint32_t)((c & 7) * 2);
#pragma unroll
            for (int mt = 0; mt < 3; mt++) {
                int r = r0 + mt * 16 + (lane >> 2);
                float2 pj0 = *(const float2*)(sPJ + r * 132 + c);
                float2 pj1 = *(const float2*)(sPJ + (r + 8) * 132 + c);
                float h00 = acc[mt][nt][0] + pix + pj0.x;
                float h01 = acc[mt][nt][1] + piy + pj0.y;
                float h10 = acc[mt][nt][2] + pix + pj1.x;
                float h11 = acc[mt][nt][3] + piy + pj1.y;
                uint32_t base  = (uint32_t)(r * 256) + (cb ^ ((uint32_t)(r & 7) << 4));
                uint32_t base8 = base + 2048;   // (r+8): same swizzle bits, +8 rows
                *(unsigned*)(smem + OFF_H + base)  = pk2(gelu_fast(h00), gelu_fast(h01));
                *(unsigned*)(smem + OFF_H + base8) = pk2(gelu_fast(h10), gelu_fast(h11));
            }
        }
        __syncthreads();

        // e: prefetch next PJ
        if (hn) { issue_pj(tn); }
        CP_COMMIT();

        // f: layer 2 MMA + gelu + row-sum over 48 edges (linearity of W3)
        run_mma(OFF_H, OFF_W2);
        float s0[2] = {0.f, 0.f}, s1[2] = {0.f, 0.f};
#pragma unroll
        for (int mt = 0; mt < 3; mt++) {
#pragma unroll
            for (int nt = 0; nt < 2; nt++) {
                int c = wn * 16 + nt * 8 + cq;
                float2 bb = *(const float2*)(sB2 + c);
                s0[nt] += gelu_fast(acc[mt][nt][0] + bb.x) + gelu_fast(acc[mt][nt][2] + bb.x);
                s1[nt] += gelu_fast(acc[mt][nt][1] + bb.y) + gelu_fast(acc[mt][nt][3] + bb.y);
            }
        }
#pragma unroll
        for (int off = 4; off < 32; off <<= 1)
#pragma unroll
            for (int nt = 0; nt < 2; nt++) {
                s0[nt] += __shfl_xor_sync(0xffffffffu, s0[nt], off);
                s1[nt] += __shfl_xor_sync(0xffffffffu, s1[nt], off);
            }
        if (lane < 4) {
#pragma unroll
            for (int nt = 0; nt < 2; nt++) {
                int c = wn * 16 + nt * 8 + lane * 2;
                float2 v; v.x = s0[nt]; v.y = s1[nt];
                *(float2*)(g_sumh2 + (size_t)(g0 + wm) * 128 + c) = v;
            }
        }
        // c-sync of this tile already ordered E reads; next a-build writes are safe
    }
}

// ---------------- final: m = sumh2@W3; u = LN(nh + (m+48b3)/30); out = LN(nh + u@Wu + bu)
#define FIN_W3 0
#define FIN_WU 16384
#define FIN_S  32768
#define FIN_U  36864
#define FIN_NH 40960
__global__ void __launch_bounds__(512)
final_kernel(const float* __restrict__ node_h, const float* __restrict__ W3,
             const float* __restrict__ b3, const float* __restrict__ Wu,
             const float* __restrict__ bu, const float* __restrict__ ln_g,
             const float* __restrict__ ln_b, float* __restrict__ out) {
    extern __shared__ float sh[];
    const uint32_t sb = smem_u32(sh);
    float* sW3 = sh + FIN_W3;
    float* sWu = sh + FIN_WU;
    float* sS  = sh + FIN_S;
    float* sU  = sh + FIN_U;
    float* sNH = sh + FIN_NH;
    int tid = threadIdx.x, lane = tid & 31, warp = tid >> 5;
    int rbase = blockIdx.x * 32;

    // group A: W3 + S + NH (phase-1 inputs)
    for (int i = tid; i < 4096; i += 512)
        cp16(sb + (FIN_W3 + i * 4) * 4, W3 + i * 4);
    for (int i = tid; i < 1024; i += 512) {
        cp16(sb + (FIN_S + i * 4) * 4, g_sumh2 + (size_t)rbase * 128 + i * 4);
        cp16(sb + (FIN_NH + i * 4) * 4, node_h + (size_t)rbase * 128 + i * 4);
    }
    CP_COMMIT();
    // group B: Wu (phase-2 input, arrives under phase-1 compute)
    for (int i = tid; i < 4096; i += 512)
        cp16(sb + (FIN_WU + i * 4) * 4, Wu + i * 4);
    CP_COMMIT();

    int c0 = lane * 4;
    float4 gv = *(const float4*)(ln_g + c0);
    float4 lv = *(const float4*)(ln_b + c0);
    float4 b3v = *(const float4*)(b3 + c0);
    float4 bv  = *(const float4*)(bu + c0);

    CP_WAIT(1);
    __syncthreads();

    // phase 1: m = S @ W3 ; u = LN(nh + (m + 48 b3)/30) -> sU   (2 rows/warp)
    float m[2][4];
#pragma unroll
    for (int r = 0; r < 2; r++)
#pragma unroll
        for (int j = 0; j < 4; j++) m[r][j] = 0.f;
#pragma unroll 4
    for (int k = 0; k < 128; k++) {
        float4 w = *(const float4*)(sW3 + k * 128 + c0);
#pragma unroll
        for (int r = 0; r < 2; r++) {
            float s = sS[(warp * 2 + r) * 128 + k];
            m[r][0] += s * w.x; m[r][1] += s * w.y;
            m[r][2] += s * w.z; m[r][3] += s * w.w;
        }
    }
#pragma unroll
    for (int r = 0; r < 2; r++) {
        int rr = warp * 2 + r;
        float4 nh = *(const float4*)(sNH + rr * 128 + c0);
        float x0 = nh.x + (m[r][0] + 48.f * b3v.x) * (1.f / 30.f);
        float x1 = nh.y + (m[r][1] + 48.f * b3v.y) * (1.f / 30.f);
        float x2 = nh.z + (m[r][2] + 48.f * b3v.z) * (1.f / 30.f);
        float x3 = nh.w + (m[r][3] + 48.f * b3v.w) * (1.f / 30.f);
        float sum = x0 + x1 + x2 + x3;
        float sq = x0 * x0 + x1 * x1 + x2 * x2 + x3 * x3;
#pragma unroll
        for (int off = 16; off; off >>= 1) {
            sum += __shfl_xor_sync(0xffffffffu, sum, off);
            sq += __shfl_xor_sync(0xffffffffu, sq, off);
        }
        float mean = sum * (1.f / 128.f);
        float var = sq * (1.f / 128.f) - mean * mean;
        float rs = rsqrtf(var + 1e-5f);
        float4 u;
        u.x = (x0 - mean) * rs * gv.x + lv.x;
        u.y = (x1 - mean) * rs * gv.y + lv.y;
        u.z = (x2 - mean) * rs * gv.z + lv.z;
        u.w = (x3 - mean) * rs * gv.w + lv.w;
        *(float4*)(sU + rr * 128 + c0) = u;
    }
    CP_WAIT(0);
    __syncthreads();

    // phase 2: y = U @ Wu ; out = LN(nh + y + bu)
    float y[2][4];
#pragma unroll
    for (int r = 0; r < 2; r++)
#pragma unroll
        for (int j = 0; j < 4; j++) y[r][j] = 0.f;
#pragma unroll 4
    for (int k = 0; k < 128; k++) {
        float4 w = *(const float4*)(sWu + k * 128 + c0);
#pragma unroll
        for (int r = 0; r < 2; r++) {
            float u = sU[(warp * 2 + r) * 128 + k];
            y[r][0] += u * w.x; y[r][1] += u * w.y;
            y[r][2] += u * w.z; y[r][3] += u * w.w;
        }
    }
#pragma unroll
    for (int r = 0; r < 2; r++) {
        int rr = warp * 2 + r;
        float4 nh = *(const float4*)(sNH + rr * 128 + c0);
        float x0 = nh.x + y[r][0] + bv.x;
        float x1 = nh.y + y[r][1] + bv.y;
        float x2 = nh.z + y[r][2] + bv.z;
        float x3 = nh.w + y[r][3] + bv.w;
        float sum = x0 + x1 + x2 + x3;
        float sq = x0 * x0 + x1 * x1 + x2 * x2 + x3 * x3;
#pragma unroll
        for (int off = 16; off; off >>= 1) {
            sum += __shfl_xor_sync(0xffffffffu, sum, off);
            sq += __shfl_xor_sync(0xffffffffu, sq, off);
        }
        float mean = sum * (1.f / 128.f);
        float var = sq * (1.f / 128.f) - mean * mean;
        float rs = rsqrtf(var + 1e-5f);
        float4 o;
        o.x = (x0 - mean) * rs * gv.x + lv.x;
        o.y = (x1 - mean) * rs * gv.y + lv.y;
        o.z = (x2 - mean) * rs * gv.z + lv.z;
        o.w = (x3 - mean) * rs * gv.w + lv.w;
        *(float4*)(out + (size_t)(rbase + rr) * 128 + c0) = o;
    }
}

// ---------------- launch ----------------
extern "C" void kernel_launch(void* const* d_in, const int* in_sizes, int n_in,
                              void* d_out, int out_size) {
    const float* node_h = (const float*)d_in[0];
    const float* edge_h = (const float*)d_in[1];
    const void* edge_index = d_in[2];
    const float* W1 = (const float*)d_in[3];
    const float* b1 = (const float*)d_in[4];
    const float* W2 = (const float*)d_in[5];
    const float* b2 = (const float*)d_in[6];
    const float* W3 = (const float*)d_in[7];
    const float* b3 = (const float*)d_in[8];
    const float* Wu = (const float*)d_in[9];
    const float* bu = (const float*)d_in[10];
    const float* ln_g = (const float*)d_in[11];
    const float* ln_b = (const float*)d_in[12];
    float* out = (float*)d_out;

    cudaFuncSetAttribute(pij_kernel, cudaFuncAttributeMaxDynamicSharedMemorySize, 147456);
    cudaFuncSetAttribute(mlp_kernel, cudaFuncAttributeMaxDynamicSharedMemorySize, SMEM_MLP);
    cudaFuncSetAttribute(final_kernel, cudaFuncAttributeMaxDynamicSharedMemorySize, 180224);

    pre_kernel<<<224, 256>>>(edge_index, W1, W2);
    pij_kernel<<<128, 256, 147456>>>(node_h, W1, b1);
    mlp_kernel<<<148, NTHR, SMEM_MLP>>>(edge_h, b2);
    final_kernel<<<128, 512, 180224>>>(node_h, W3, b3, Wu, bu, ln_g, ln_b, out);
}